// round 2
// baseline (speedup 1.0000x reference)
#include <cuda_runtime.h>
#include <cstdint>
#include <math.h>

// ---------------------------------------------------------------------------
// TokenPacker R2: pre-rounded tf32 operands (no in-loop cvt), 256x128 CTA
// tile / 64x64 warp tile, 4-stage cp.async pipeline, dynamic smem.
// ---------------------------------------------------------------------------

#define E_DIM   1024
#define N_IMG   64
#define NQ_TOK  144
#define TN_TOK  576
#define M_BIG   (N_IMG * TN_TOK)   // 36864
#define M_SMALL (N_IMG * NQ_TOK)   // 9216
#define NKT     64                 // K / 16
#define STAGES  4
#define SSTRIDE 20                 // smem row stride (floats), conflict-free reads
#define BM      256
#define BN      128

// Scratch (device statics; no cudaMalloc allowed)
__device__ __align__(256) float g_h  [(size_t)M_BIG   * E_DIM];
__device__ __align__(256) float g_key[(size_t)M_BIG   * E_DIM];
__device__ __align__(256) float g_val[(size_t)M_BIG   * E_DIM];
__device__ __align__(256) float g_kh [(size_t)M_BIG   * E_DIM];
__device__ __align__(256) float g_vh [(size_t)M_BIG   * E_DIM];
__device__ __align__(256) float g_q  [(size_t)M_SMALL * E_DIM];
__device__ __align__(256) float g_qh [(size_t)M_SMALL * E_DIM];
__device__ __align__(256) float g_o  [(size_t)M_SMALL * E_DIM];
__device__ __align__(256) float g_xr [(size_t)M_SMALL * E_DIM];   // rounded x
__device__ __align__(256) float g_xfr[(size_t)M_BIG   * E_DIM];   // rounded x_feat
__device__ __align__(256) float g_wt [9ull * 1024 * 1024];        // rounded weights

__device__ __forceinline__ float rnd_tf32(float f) {
    uint32_t r;
    asm("cvt.rna.tf32.f32 %0, %1;" : "=r"(r) : "f"(f));
    return __uint_as_float(r);
}

__device__ __forceinline__ float gelu_exact(float x) {
    return 0.5f * x * (1.0f + erff(x * 0.70710678118654752f));
}

#define CP_ASYNC16(smem_u32, gptr) \
    asm volatile("cp.async.cg.shared.global [%0], [%1], 16;\n" :: "r"(smem_u32), "l"(gptr))

// ---------------------------------------------------------------------------
// Elementwise tf32 rounding prepass
// ---------------------------------------------------------------------------
__global__ void round_tf32_kernel(const float4* __restrict__ in,
                                  float4* __restrict__ out, int n4)
{
    int i = blockIdx.x * blockDim.x + threadIdx.x;
    if (i < n4) {
        float4 v = in[i];
        v.x = rnd_tf32(v.x); v.y = rnd_tf32(v.y);
        v.z = rnd_tf32(v.z); v.w = rnd_tf32(v.w);
        out[i] = v;
    }
}

// ---------------------------------------------------------------------------
// GEMM: C[M x 1024] = act(A[M x 1024] @ W[1024 x 1024]^T + bias)
// A and W must already be tf32-rounded. ACT: 0=none 1=GELU. RND: round output.
// 256x128 tile, 256 threads, 8 warps of 64x64, mma.sync.m16n8k8.tf32,
// 4-stage cp.async pipeline. M % 256 == 0, N = K = 1024.
// ---------------------------------------------------------------------------
template <int ACT, int RND>
__global__ __launch_bounds__(256)
void gemm_tf32(const float* __restrict__ A, const float* __restrict__ W,
               const float* __restrict__ bias, float* __restrict__ C)
{
    extern __shared__ float sm[];
    float* As = sm;                               // [STAGES][BM][SSTRIDE]
    float* Bs = sm + STAGES * BM * SSTRIDE;       // [STAGES][BN][SSTRIDE]

    const int tid  = threadIdx.x;
    const int warp = tid >> 5;
    const int lane = tid & 31;
    const int grp  = lane >> 2;   // 0..7
    const int tig  = lane & 3;    // 0..3
    const int wm   = (warp & 3) * 64;
    const int wn   = (warp >> 2) * 64;
    const int row0 = blockIdx.y * BM;
    const int col0 = blockIdx.x * BN;

    float acc[4][8][4];
    #pragma unroll
    for (int i = 0; i < 4; i++)
        #pragma unroll
        for (int j = 0; j < 8; j++)
            #pragma unroll
            for (int k = 0; k < 4; k++) acc[i][j][k] = 0.0f;

    const int lr = tid >> 2;          // 0..63
    const int lc = (tid & 3) * 4;     // float col 0,4,8,12

    const float* Abase = A + (size_t)(row0 + lr) * E_DIM + lc;
    const float* Wbase = W + (size_t)(col0 + lr) * E_DIM + lc;

    // prologue: prefetch kt = 0,1,2
    #pragma unroll
    for (int kt = 0; kt < 3; kt++) {
        float* as = As + kt * BM * SSTRIDE;
        float* bs = Bs + kt * BN * SSTRIDE;
        #pragma unroll
        for (int i = 0; i < 4; i++)
            CP_ASYNC16((uint32_t)__cvta_generic_to_shared(&as[(lr + i * 64) * SSTRIDE + lc]),
                       Abase + (size_t)i * 64 * E_DIM + kt * 16);
        #pragma unroll
        for (int i = 0; i < 2; i++)
            CP_ASYNC16((uint32_t)__cvta_generic_to_shared(&bs[(lr + i * 64) * SSTRIDE + lc]),
                       Wbase + (size_t)i * 64 * E_DIM + kt * 16);
        asm volatile("cp.async.commit_group;\n");
    }

    for (int kt = 0; kt < NKT; kt++) {
        asm volatile("cp.async.wait_group 2;\n");
        __syncthreads();   // stage kt ready; all warps done reading stage (kt+3)&3

        const int pf = kt + 3;
        if (pf < NKT) {
            float* as = As + (pf & 3) * BM * SSTRIDE;
            float* bs = Bs + (pf & 3) * BN * SSTRIDE;
            #pragma unroll
            for (int i = 0; i < 4; i++)
                CP_ASYNC16((uint32_t)__cvta_generic_to_shared(&as[(lr + i * 64) * SSTRIDE + lc]),
                           Abase + (size_t)i * 64 * E_DIM + pf * 16);
            #pragma unroll
            for (int i = 0; i < 2; i++)
                CP_ASYNC16((uint32_t)__cvta_generic_to_shared(&bs[(lr + i * 64) * SSTRIDE + lc]),
                           Wbase + (size_t)i * 64 * E_DIM + pf * 16);
        }
        asm volatile("cp.async.commit_group;\n");

        const float* a = As + (kt & 3) * BM * SSTRIDE;
        const float* b = Bs + (kt & 3) * BN * SSTRIDE;

        #pragma unroll
        for (int ks = 0; ks < 2; ks++) {
            const int k0 = ks * 8;
            uint32_t af[4][4], bf[8][2];
            #pragma unroll
            for (int mi = 0; mi < 4; mi++) {
                const int r = wm + mi * 16 + grp;
                af[mi][0] = __float_as_uint(a[r * SSTRIDE + k0 + tig]);
                af[mi][1] = __float_as_uint(a[(r + 8) * SSTRIDE + k0 + tig]);
                af[mi][2] = __float_as_uint(a[r * SSTRIDE + k0 + tig + 4]);
                af[mi][3] = __float_as_uint(a[(r + 8) * SSTRIDE + k0 + tig + 4]);
            }
            #pragma unroll
            for (int ni = 0; ni < 8; ni++) {
                const int c = wn + ni * 8 + grp;
                bf[ni][0] = __float_as_uint(b[c * SSTRIDE + k0 + tig]);
                bf[ni][1] = __float_as_uint(b[c * SSTRIDE + k0 + tig + 4]);
            }
            #pragma unroll
            for (int mi = 0; mi < 4; mi++)
                #pragma unroll
                for (int ni = 0; ni < 8; ni++)
                    asm volatile(
                        "mma.sync.aligned.m16n8k8.row.col.f32.tf32.tf32.f32 "
                        "{%0,%1,%2,%3}, {%4,%5,%6,%7}, {%8,%9}, {%0,%1,%2,%3};\n"
                        : "+f"(acc[mi][ni][0]), "+f"(acc[mi][ni][1]),
                          "+f"(acc[mi][ni][2]), "+f"(acc[mi][ni][3])
                        : "r"(af[mi][0]), "r"(af[mi][1]), "r"(af[mi][2]), "r"(af[mi][3]),
                          "r"(bf[ni][0]), "r"(bf[ni][1]));
        }
    }

    // epilogue: bias + activation (+ tf32 rounding), float2 stores
    #pragma unroll
    for (int ni = 0; ni < 8; ni++) {
        const int col = col0 + wn + ni * 8 + tig * 2;
        float bv0 = 0.0f, bv1 = 0.0f;
        if (bias) { bv0 = bias[col]; bv1 = bias[col + 1]; }
        #pragma unroll
        for (int mi = 0; mi < 4; mi++) {
            #pragma unroll
            for (int half = 0; half < 2; half++) {
                const int row = row0 + wm + mi * 16 + grp + half * 8;
                float v0 = acc[mi][ni][half * 2 + 0] + bv0;
                float v1 = acc[mi][ni][half * 2 + 1] + bv1;
                if (ACT == 1) { v0 = gelu_exact(v0); v1 = gelu_exact(v1); }
                if (RND == 1) { v0 = rnd_tf32(v0); v1 = rnd_tf32(v1); }
                *(float2*)(C + (size_t)row * E_DIM + col) = make_float2(v0, v1);
            }
        }
    }
}

// ---------------------------------------------------------------------------
// In-place LayerNorm over rows of 1024 (eps=1e-6); output tf32-rounded
// (consumers are all tensor-core GEMMs which would round anyway).
// ---------------------------------------------------------------------------
__global__ void ln_kernel(float* __restrict__ data,
                          const float* __restrict__ w, const float* __restrict__ b)
{
    const int row = blockIdx.x;
    float4* p = (float4*)(data + (size_t)row * E_DIM);
    float4 v = p[threadIdx.x];
    float s = v.x + v.y + v.z + v.w;
    float q = v.x * v.x + v.y * v.y + v.z * v.z + v.w * v.w;
    #pragma unroll
    for (int o = 16; o; o >>= 1) {
        s += __shfl_xor_sync(0xffffffffu, s, o);
        q += __shfl_xor_sync(0xffffffffu, q, o);
    }
    __shared__ float ss[8], sq[8];
    const int warp = threadIdx.x >> 5, lane = threadIdx.x & 31;
    if (lane == 0) { ss[warp] = s; sq[warp] = q; }
    __syncthreads();
    if (warp == 0) {
        s = (lane < 8) ? ss[lane] : 0.0f;
        q = (lane < 8) ? sq[lane] : 0.0f;
        #pragma unroll
        for (int o = 4; o; o >>= 1) {
            s += __shfl_xor_sync(0xffffffffu, s, o);
            q += __shfl_xor_sync(0xffffffffu, q, o);
        }
        if (lane == 0) { ss[0] = s; sq[0] = q; }
    }
    __syncthreads();
    const float mean = ss[0] * (1.0f / 1024.0f);
    const float var  = sq[0] * (1.0f / 1024.0f) - mean * mean;
    const float rstd = rsqrtf(var + 1e-6f);
    const float4 wv = ((const float4*)w)[threadIdx.x];
    const float4 bv = ((const float4*)b)[threadIdx.x];
    v.x = rnd_tf32((v.x - mean) * rstd * wv.x + bv.x);
    v.y = rnd_tf32((v.y - mean) * rstd * wv.y + bv.y);
    v.z = rnd_tf32((v.z - mean) * rstd * wv.z + bv.z);
    v.w = rnd_tf32((v.w - mean) * rstd * wv.w + bv.w);
    p[threadIdx.x] = v;
}

// ---------------------------------------------------------------------------
// Attention: q len 1 over its 2x2 key patch; output tf32-rounded (feeds GEMM).
// ---------------------------------------------------------------------------
__global__ void attn_kernel(const float* __restrict__ qh, const float* __restrict__ kh,
                            const float* __restrict__ vh, float* __restrict__ o)
{
    const int r  = blockIdx.x;
    const int n  = r / NQ_TOK;
    const int qi = r - n * NQ_TOK;
    const int ar = qi / 12;
    const int ac = qi - ar * 12;
    const int head = threadIdx.x >> 5, lane = threadIdx.x & 31;
    const size_t qoff = (size_t)r * E_DIM + head * 128 + lane * 4;
    const float4 qv = *(const float4*)(qh + qoff);

    int trow[4];
    #pragma unroll
    for (int j = 0; j < 4; j++)
        trow[j] = n * TN_TOK + (2 * ar + (j >> 1)) * 24 + (2 * ac + (j & 1));

    float s[4];
    #pragma unroll
    for (int j = 0; j < 4; j++) {
        const float4 kv = *(const float4*)(kh + (size_t)trow[j] * E_DIM + head * 128 + lane * 4);
        float d = qv.x * kv.x + qv.y * kv.y + qv.z * kv.z + qv.w * kv.w;
        #pragma unroll
        for (int off = 16; off; off >>= 1) d += __shfl_xor_sync(0xffffffffu, d, off);
        s[j] = d * 0.08838834764831843f;
    }
    const float m = fmaxf(fmaxf(s[0], s[1]), fmaxf(s[2], s[3]));
    float e[4], tot = 0.0f;
    #pragma unroll
    for (int j = 0; j < 4; j++) { e[j] = expf(s[j] - m); tot += e[j]; }
    const float inv = 1.0f / tot;

    float4 acc = make_float4(0.f, 0.f, 0.f, 0.f);
    #pragma unroll
    for (int j = 0; j < 4; j++) {
        const float p = e[j] * inv;
        const float4 vv = *(const float4*)(vh + (size_t)trow[j] * E_DIM + head * 128 + lane * 4);
        acc.x += p * vv.x; acc.y += p * vv.y; acc.z += p * vv.z; acc.w += p * vv.w;
    }
    acc.x = rnd_tf32(acc.x); acc.y = rnd_tf32(acc.y);
    acc.z = rnd_tf32(acc.z); acc.w = rnd_tf32(acc.w);
    *(float4*)(o + qoff) = acc;
}

// ---------------------------------------------------------------------------
extern "C" void kernel_launch(void* const* d_in, const int* in_sizes, int n_in,
                              void* d_out, int out_size)
{
    const float* x      = (const float*)d_in[0];
    const float* x_feat = (const float*)d_in[1];
    const float* w_q    = (const float*)d_in[2];
    const float* w_k1   = (const float*)d_in[3];
    const float* b_k1   = (const float*)d_in[4];
    const float* w_k2   = (const float*)d_in[5];
    const float* b_k2   = (const float*)d_in[6];
    const float* w_v1   = (const float*)d_in[7];
    const float* b_v1   = (const float*)d_in[8];
    const float* w_v2   = (const float*)d_in[9];
    const float* b_v2   = (const float*)d_in[10];
    const float* ln_q_w = (const float*)d_in[11];
    const float* ln_q_b = (const float*)d_in[12];
    const float* ln_k_w = (const float*)d_in[13];
    const float* ln_k_b = (const float*)d_in[14];
    const float* ln_v_w = (const float*)d_in[15];
    const float* ln_v_b = (const float*)d_in[16];
    const float* in_w   = (const float*)d_in[17];
    const float* in_b   = (const float*)d_in[18];
    const float* out_w  = (const float*)d_in[19];
    const float* out_b  = (const float*)d_in[20];

    float *h, *key, *val, *kh, *vh, *qb, *qh, *o, *xr, *xfr, *wt;
    cudaGetSymbolAddress((void**)&h,   g_h);
    cudaGetSymbolAddress((void**)&key, g_key);
    cudaGetSymbolAddress((void**)&val, g_val);
    cudaGetSymbolAddress((void**)&kh,  g_kh);
    cudaGetSymbolAddress((void**)&vh,  g_vh);
    cudaGetSymbolAddress((void**)&qb,  g_q);
    cudaGetSymbolAddress((void**)&qh,  g_qh);
    cudaGetSymbolAddress((void**)&o,   g_o);
    cudaGetSymbolAddress((void**)&xr,  g_xr);
    cudaGetSymbolAddress((void**)&xfr, g_xfr);
    cudaGetSymbolAddress((void**)&wt,  g_wt);

    const size_t MW = 1024ull * 1024ull;
    float* wt_q   = wt;
    float* wt_k1  = wt + 1 * MW;
    float* wt_k2  = wt + 2 * MW;
    float* wt_v1  = wt + 3 * MW;
    float* wt_v2  = wt + 4 * MW;
    float* wt_in  = wt + 5 * MW;   // 3 MW
    float* wt_out = wt + 8 * MW;

    const int smem_bytes = STAGES * (BM + BN) * SSTRIDE * 4;  // 122880
    cudaFuncSetAttribute(gemm_tf32<0, 0>, cudaFuncAttributeMaxDynamicSharedMemorySize, smem_bytes);
    cudaFuncSetAttribute(gemm_tf32<1, 1>, cudaFuncAttributeMaxDynamicSharedMemorySize, smem_bytes);

    // ---- prepass: tf32-round inputs + weights ----
    {
        const int T = 256;
        int n4;
        n4 = M_SMALL * E_DIM / 4;
        round_tf32_kernel<<<(n4 + T - 1) / T, T>>>((const float4*)x, (float4*)xr, n4);
        n4 = M_BIG * E_DIM / 4;
        round_tf32_kernel<<<(n4 + T - 1) / T, T>>>((const float4*)x_feat, (float4*)xfr, n4);
        n4 = (int)(MW / 4);
        round_tf32_kernel<<<(n4 + T - 1) / T, T>>>((const float4*)w_q,  (float4*)wt_q,  n4);
        round_tf32_kernel<<<(n4 + T - 1) / T, T>>>((const float4*)w_k1, (float4*)wt_k1, n4);
        round_tf32_kernel<<<(n4 + T - 1) / T, T>>>((const float4*)w_k2, (float4*)wt_k2, n4);
        round_tf32_kernel<<<(n4 + T - 1) / T, T>>>((const float4*)w_v1, (float4*)wt_v1, n4);
        round_tf32_kernel<<<(n4 + T - 1) / T, T>>>((const float4*)w_v2, (float4*)wt_v2, n4);
        n4 = (int)(3 * MW / 4);
        round_tf32_kernel<<<(n4 + T - 1) / T, T>>>((const float4*)in_w, (float4*)wt_in, n4);
        n4 = (int)(MW / 4);
        round_tf32_kernel<<<(n4 + T - 1) / T, T>>>((const float4*)out_w, (float4*)wt_out, n4);
    }

    const dim3 blk(256);
    const dim3 gBig(8, M_BIG / BM);    // (8, 144)
    const dim3 gSm(8, M_SMALL / BM);   // (8, 36)

    // K path
    gemm_tf32<1, 1><<<gBig, blk, smem_bytes>>>(xfr, wt_k1, b_k1, h);
    gemm_tf32<0, 0><<<gBig, blk, smem_bytes>>>(h, wt_k2, b_k2, key);
    ln_kernel<<<M_BIG, 256>>>(key, ln_k_w, ln_k_b);
    // V path
    gemm_tf32<1, 1><<<gBig, blk, smem_bytes>>>(xfr, wt_v1, b_v1, h);
    gemm_tf32<0, 0><<<gBig, blk, smem_bytes>>>(h, wt_v2, b_v2, val);
    ln_kernel<<<M_BIG, 256>>>(val, ln_v_w, ln_v_b);
    // Q path
    gemm_tf32<0, 0><<<gSm, blk, smem_bytes>>>(xr, wt_q, nullptr, qb);
    ln_kernel<<<M_SMALL, 256>>>(qb, ln_q_w, ln_q_b);
    // in_proj
    gemm_tf32<0, 0><<<gSm,  blk, smem_bytes>>>(qb,  wt_in,          in_b,        qh);
    gemm_tf32<0, 0><<<gBig, blk, smem_bytes>>>(key, wt_in + MW,     in_b + 1024, kh);
    gemm_tf32<0, 0><<<gBig, blk, smem_bytes>>>(val, wt_in + 2 * MW, in_b + 2048, vh);
    // attention
    attn_kernel<<<M_SMALL, 256>>>(qh, kh, vh, o);
    // out_proj -> d_out
    gemm_tf32<0, 0><<<gSm, blk, smem_bytes>>>(o, wt_out, out_b, (float*)d_out);
}

// round 4
// speedup vs baseline: 1.0191x; 1.0191x over previous
#include <cuda_runtime.h>
#include <cstdint>
#include <math.h>

// ---------------------------------------------------------------------------
// TokenPacker R4: mma.sync tf32 GEMM, 128x128 CTA tile (2 CTAs/SM), operands
// pre-rounded to tf32 (no in-loop cvt), 4-stage cp.async pipeline.
// tcgen05 unavailable: harness ptxas targets sm_100 (no 'a' features).
// ---------------------------------------------------------------------------

#define E_DIM   1024
#define N_IMG   64
#define NQ_TOK  144
#define TN_TOK  576
#define M_BIG   (N_IMG * TN_TOK)   // 36864
#define M_SMALL (N_IMG * NQ_TOK)   // 9216
#define NKT     64                 // K / 16
#define STAGES  4
#define SSTRIDE 20                 // smem row stride (floats), conflict-free
#define BM      128
#define BN      128

// Scratch (device statics; no cudaMalloc allowed)
__device__ __align__(256) float g_h  [(size_t)M_BIG   * E_DIM];
__device__ __align__(256) float g_key[(size_t)M_BIG   * E_DIM];
__device__ __align__(256) float g_val[(size_t)M_BIG   * E_DIM];
__device__ __align__(256) float g_kh [(size_t)M_BIG   * E_DIM];
__device__ __align__(256) float g_vh [(size_t)M_BIG   * E_DIM];
__device__ __align__(256) float g_q  [(size_t)M_SMALL * E_DIM];
__device__ __align__(256) float g_qh [(size_t)M_SMALL * E_DIM];
__device__ __align__(256) float g_o  [(size_t)M_SMALL * E_DIM];
__device__ __align__(256) float g_xr [(size_t)M_SMALL * E_DIM];
__device__ __align__(256) float g_xfr[(size_t)M_BIG   * E_DIM];
__device__ __align__(256) float g_wt [9ull * 1024 * 1024];

__device__ __forceinline__ float rnd_tf32(float f) {
    uint32_t r;
    asm("cvt.rna.tf32.f32 %0, %1;" : "=r"(r) : "f"(f));
    return __uint_as_float(r);
}

__device__ __forceinline__ float gelu_exact(float x) {
    return 0.5f * x * (1.0f + erff(x * 0.70710678118654752f));
}

#define CP_ASYNC16(smem_u32a, gptr) \
    asm volatile("cp.async.cg.shared.global [%0], [%1], 16;\n" :: "r"(smem_u32a), "l"(gptr))

// ---------------------------------------------------------------------------
// tf32 rounding prepass
// ---------------------------------------------------------------------------
__global__ void round_tf32_kernel(const float4* __restrict__ in,
                                  float4* __restrict__ out, int n4)
{
    int i = blockIdx.x * blockDim.x + threadIdx.x;
    if (i < n4) {
        float4 v = in[i];
        v.x = rnd_tf32(v.x); v.y = rnd_tf32(v.y);
        v.z = rnd_tf32(v.z); v.w = rnd_tf32(v.w);
        out[i] = v;
    }
}

// ---------------------------------------------------------------------------
// GEMM: C[M x 1024] = act(A[M x 1024] @ W[1024 x 1024]^T + bias)
// A and W pre-rounded tf32. ACT: 0=none 1=GELU. RND: round output to tf32.
// 128x128 tile, 256 threads, 8 warps of 64x32, mma.sync.m16n8k8.tf32,
// 4-stage cp.async pipeline. M % 128 == 0, N = K = 1024.
// ---------------------------------------------------------------------------
template <int ACT, int RND>
__global__ __launch_bounds__(256, 2)
void gemm_tf32(const float* __restrict__ A, const float* __restrict__ W,
               const float* __restrict__ bias, float* __restrict__ C)
{
    extern __shared__ float sm[];
    float* As = sm;                               // [STAGES][BM][SSTRIDE]
    float* Bs = sm + STAGES * BM * SSTRIDE;       // [STAGES][BN][SSTRIDE]

    const int tid  = threadIdx.x;
    const int warp = tid >> 5;
    const int lane = tid & 31;
    const int grp  = lane >> 2;   // 0..7
    const int tig  = lane & 3;    // 0..3
    const int wm   = (warp & 1) * 64;
    const int wn   = (warp >> 1) * 32;
    const int row0 = blockIdx.y * BM;
    const int col0 = blockIdx.x * BN;

    float acc[4][4][4];
    #pragma unroll
    for (int i = 0; i < 4; i++)
        #pragma unroll
        for (int j = 0; j < 4; j++)
            #pragma unroll
            for (int k = 0; k < 4; k++) acc[i][j][k] = 0.0f;

    const int lr0 = tid >> 2;         // 0..63
    const int lc  = (tid & 3) * 4;    // float col 0,4,8,12

    const float* Abase = A + (size_t)(row0 + lr0) * E_DIM + lc;
    const float* Wbase = W + (size_t)(col0 + lr0) * E_DIM + lc;

    // prologue: prefetch kt = 0,1,2
    #pragma unroll
    for (int kt = 0; kt < 3; kt++) {
        float* as = As + kt * BM * SSTRIDE;
        float* bs = Bs + kt * BN * SSTRIDE;
        #pragma unroll
        for (int i = 0; i < 2; i++) {
            CP_ASYNC16((uint32_t)__cvta_generic_to_shared(&as[(lr0 + i * 64) * SSTRIDE + lc]),
                       Abase + (size_t)i * 64 * E_DIM + kt * 16);
            CP_ASYNC16((uint32_t)__cvta_generic_to_shared(&bs[(lr0 + i * 64) * SSTRIDE + lc]),
                       Wbase + (size_t)i * 64 * E_DIM + kt * 16);
        }
        asm volatile("cp.async.commit_group;\n");
    }

    for (int kt = 0; kt < NKT; kt++) {
        asm volatile("cp.async.wait_group 2;\n");
        __syncthreads();   // stage kt ready; all warps done reading stage (kt+3)&3

        const int pf = kt + 3;
        if (pf < NKT) {
            float* as = As + (pf & 3) * BM * SSTRIDE;
            float* bs = Bs + (pf & 3) * BN * SSTRIDE;
            #pragma unroll
            for (int i = 0; i < 2; i++) {
                CP_ASYNC16((uint32_t)__cvta_generic_to_shared(&as[(lr0 + i * 64) * SSTRIDE + lc]),
                           Abase + (size_t)i * 64 * E_DIM + pf * 16);
                CP_ASYNC16((uint32_t)__cvta_generic_to_shared(&bs[(lr0 + i * 64) * SSTRIDE + lc]),
                           Wbase + (size_t)i * 64 * E_DIM + pf * 16);
            }
        }
        asm volatile("cp.async.commit_group;\n");

        const float* a = As + (kt & 3) * BM * SSTRIDE;
        const float* b = Bs + (kt & 3) * BN * SSTRIDE;

        #pragma unroll
        for (int ks = 0; ks < 2; ks++) {
            const int k0 = ks * 8;
            uint32_t af[4][4], bf[4][2];
            #pragma unroll
            for (int mi = 0; mi < 4; mi++) {
                const int r = wm + mi * 16 + grp;
                af[mi][0] = __float_as_uint(a[r * SSTRIDE + k0 + tig]);
                af[mi][1] = __float_as_uint(a[(r + 8) * SSTRIDE + k0 + tig]);
                af[mi][2] = __float_as_uint(a[r * SSTRIDE + k0 + tig + 4]);
                af[mi][3] = __float_as_uint(a[(r + 8) * SSTRIDE + k0 + tig + 4]);
            }
            #pragma unroll
            for (int ni = 0; ni < 4; ni++) {
                const int c = wn + ni * 8 + grp;
                bf[ni][0] = __float_as_uint(b[c * SSTRIDE + k0 + tig]);
                bf[ni][1] = __float_as_uint(b[c * SSTRIDE + k0 + tig + 4]);
            }
            #pragma unroll
            for (int mi = 0; mi < 4; mi++)
                #pragma unroll
                for (int ni = 0; ni < 4; ni++)
                    asm volatile(
                        "mma.sync.aligned.m16n8k8.row.col.f32.tf32.tf32.f32 "
                        "{%0,%1,%2,%3}, {%4,%5,%6,%7}, {%8,%9}, {%0,%1,%2,%3};\n"
                        : "+f"(acc[mi][ni][0]), "+f"(acc[mi][ni][1]),
                          "+f"(acc[mi][ni][2]), "+f"(acc[mi][ni][3])
                        : "r"(af[mi][0]), "r"(af[mi][1]), "r"(af[mi][2]), "r"(af[mi][3]),
                          "r"(bf[ni][0]), "r"(bf[ni][1]));
        }
    }

    // epilogue: bias + activation (+ tf32 rounding), float2 stores
    #pragma unroll
    for (int ni = 0; ni < 4; ni++) {
        const int col = col0 + wn + ni * 8 + tig * 2;
        float bv0 = 0.0f, bv1 = 0.0f;
        if (bias) { bv0 = bias[col]; bv1 = bias[col + 1]; }
        #pragma unroll
        for (int mi = 0; mi < 4; mi++) {
            #pragma unroll
            for (int half = 0; half < 2; half++) {
                const int row = row0 + wm + mi * 16 + grp + half * 8;
                float v0 = acc[mi][ni][half * 2 + 0] + bv0;
                float v1 = acc[mi][ni][half * 2 + 1] + bv1;
                if (ACT == 1) { v0 = gelu_exact(v0); v1 = gelu_exact(v1); }
                if (RND == 1) { v0 = rnd_tf32(v0); v1 = rnd_tf32(v1); }
                *(float2*)(C + (size_t)row * E_DIM + col) = make_float2(v0, v1);
            }
        }
    }
}

// ---------------------------------------------------------------------------
// In-place LayerNorm over rows of 1024 (eps=1e-6); output tf32-rounded.
// ---------------------------------------------------------------------------
__global__ void ln_kernel(float* __restrict__ data,
                          const float* __restrict__ w, const float* __restrict__ b)
{
    const int row = blockIdx.x;
    float4* p = (float4*)(data + (size_t)row * E_DIM);
    float4 v = p[threadIdx.x];
    float s = v.x + v.y + v.z + v.w;
    float q = v.x * v.x + v.y * v.y + v.z * v.z + v.w * v.w;
    #pragma unroll
    for (int o = 16; o; o >>= 1) {
        s += __shfl_xor_sync(0xffffffffu, s, o);
        q += __shfl_xor_sync(0xffffffffu, q, o);
    }
    __shared__ float ss[8], sq[8];
    const int warp = threadIdx.x >> 5, lane = threadIdx.x & 31;
    if (lane == 0) { ss[warp] = s; sq[warp] = q; }
    __syncthreads();
    if (warp == 0) {
        s = (lane < 8) ? ss[lane] : 0.0f;
        q = (lane < 8) ? sq[lane] : 0.0f;
        #pragma unroll
        for (int o = 4; o; o >>= 1) {
            s += __shfl_xor_sync(0xffffffffu, s, o);
            q += __shfl_xor_sync(0xffffffffu, q, o);
        }
        if (lane == 0) { ss[0] = s; sq[0] = q; }
    }
    __syncthreads();
    const float mean = ss[0] * (1.0f / 1024.0f);
    const float var  = sq[0] * (1.0f / 1024.0f) - mean * mean;
    const float rstd = rsqrtf(var + 1e-6f);
    const float4 wv = ((const float4*)w)[threadIdx.x];
    const float4 bv = ((const float4*)b)[threadIdx.x];
    v.x = rnd_tf32((v.x - mean) * rstd * wv.x + bv.x);
    v.y = rnd_tf32((v.y - mean) * rstd * wv.y + bv.y);
    v.z = rnd_tf32((v.z - mean) * rstd * wv.z + bv.z);
    v.w = rnd_tf32((v.w - mean) * rstd * wv.w + bv.w);
    p[threadIdx.x] = v;
}

// ---------------------------------------------------------------------------
// Attention: q len 1 over its 2x2 key patch; output tf32-rounded.
// ---------------------------------------------------------------------------
__global__ void attn_kernel(const float* __restrict__ qh, const float* __restrict__ kh,
                            const float* __restrict__ vh, float* __restrict__ o)
{
    const int r  = blockIdx.x;
    const int n  = r / NQ_TOK;
    const int qi = r - n * NQ_TOK;
    const int ar = qi / 12;
    const int ac = qi - ar * 12;
    const int head = threadIdx.x >> 5, lane = threadIdx.x & 31;
    const size_t qoff = (size_t)r * E_DIM + head * 128 + lane * 4;
    const float4 qv = *(const float4*)(qh + qoff);

    int trow[4];
    #pragma unroll
    for (int j = 0; j < 4; j++)
        trow[j] = n * TN_TOK + (2 * ar + (j >> 1)) * 24 + (2 * ac + (j & 1));

    float s[4];
    #pragma unroll
    for (int j = 0; j < 4; j++) {
        const float4 kv = *(const float4*)(kh + (size_t)trow[j] * E_DIM + head * 128 + lane * 4);
        float d = qv.x * kv.x + qv.y * kv.y + qv.z * kv.z + qv.w * kv.w;
        #pragma unroll
        for (int off = 16; off; off >>= 1) d += __shfl_xor_sync(0xffffffffu, d, off);
        s[j] = d * 0.08838834764831843f;
    }
    const float m = fmaxf(fmaxf(s[0], s[1]), fmaxf(s[2], s[3]));
    float e[4], tot = 0.0f;
    #pragma unroll
    for (int j = 0; j < 4; j++) { e[j] = expf(s[j] - m); tot += e[j]; }
    const float inv = 1.0f / tot;

    float4 acc = make_float4(0.f, 0.f, 0.f, 0.f);
    #pragma unroll
    for (int j = 0; j < 4; j++) {
        const float p = e[j] * inv;
        const float4 vv = *(const float4*)(vh + (size_t)trow[j] * E_DIM + head * 128 + lane * 4);
        acc.x += p * vv.x; acc.y += p * vv.y; acc.z += p * vv.z; acc.w += p * vv.w;
    }
    acc.x = rnd_tf32(acc.x); acc.y = rnd_tf32(acc.y);
    acc.z = rnd_tf32(acc.z); acc.w = rnd_tf32(acc.w);
    *(float4*)(o + qoff) = acc;
}

// ---------------------------------------------------------------------------
extern "C" void kernel_launch(void* const* d_in, const int* in_sizes, int n_in,
                              void* d_out, int out_size)
{
    const float* x      = (const float*)d_in[0];
    const float* x_feat = (const float*)d_in[1];
    const float* w_q    = (const float*)d_in[2];
    const float* w_k1   = (const float*)d_in[3];
    const float* b_k1   = (const float*)d_in[4];
    const float* w_k2   = (const float*)d_in[5];
    const float* b_k2   = (const float*)d_in[6];
    const float* w_v1   = (const float*)d_in[7];
    const float* b_v1   = (const float*)d_in[8];
    const float* w_v2   = (const float*)d_in[9];
    const float* b_v2   = (const float*)d_in[10];
    const float* ln_q_w = (const float*)d_in[11];
    const float* ln_q_b = (const float*)d_in[12];
    const float* ln_k_w = (const float*)d_in[13];
    const float* ln_k_b = (const float*)d_in[14];
    const float* ln_v_w = (const float*)d_in[15];
    const float* ln_v_b = (const float*)d_in[16];
    const float* in_w   = (const float*)d_in[17];
    const float* in_b   = (const float*)d_in[18];
    const float* out_w  = (const float*)d_in[19];
    const float* out_b  = (const float*)d_in[20];

    float *h, *key, *val, *kh, *vh, *qb, *qh, *o, *xr, *xfr, *wt;
    cudaGetSymbolAddress((void**)&h,   g_h);
    cudaGetSymbolAddress((void**)&key, g_key);
    cudaGetSymbolAddress((void**)&val, g_val);
    cudaGetSymbolAddress((void**)&kh,  g_kh);
    cudaGetSymbolAddress((void**)&vh,  g_vh);
    cudaGetSymbolAddress((void**)&qb,  g_q);
    cudaGetSymbolAddress((void**)&qh,  g_qh);
    cudaGetSymbolAddress((void**)&o,   g_o);
    cudaGetSymbolAddress((void**)&xr,  g_xr);
    cudaGetSymbolAddress((void**)&xfr, g_xfr);
    cudaGetSymbolAddress((void**)&wt,  g_wt);

    const size_t MW = 1024ull * 1024ull;
    float* wt_q   = wt;
    float* wt_k1  = wt + 1 * MW;
    float* wt_k2  = wt + 2 * MW;
    float* wt_v1  = wt + 3 * MW;
    float* wt_v2  = wt + 4 * MW;
    float* wt_in  = wt + 5 * MW;   // 3 MW
    float* wt_out = wt + 8 * MW;

    const int smem_bytes = STAGES * (BM + BN) * SSTRIDE * 4;  // 81920
    cudaFuncSetAttribute(gemm_tf32<0, 0>, cudaFuncAttributeMaxDynamicSharedMemorySize, smem_bytes);
    cudaFuncSetAttribute(gemm_tf32<0, 1>, cudaFuncAttributeMaxDynamicSharedMemorySize, smem_bytes);
    cudaFuncSetAttribute(gemm_tf32<1, 1>, cudaFuncAttributeMaxDynamicSharedMemorySize, smem_bytes);

    // prepass: tf32-round inputs + weights
    {
        const int T = 256;
        int n4;
        n4 = M_SMALL * E_DIM / 4;
        round_tf32_kernel<<<(n4 + T - 1) / T, T>>>((const float4*)x, (float4*)xr, n4);
        n4 = M_BIG * E_DIM / 4;
        round_tf32_kernel<<<(n4 + T - 1) / T, T>>>((const float4*)x_feat, (float4*)xfr, n4);
        n4 = (int)(MW / 4);
        round_tf32_kernel<<<(n4 + T - 1) / T, T>>>((const float4*)w_q,  (float4*)wt_q,  n4);
        round_tf32_kernel<<<(n4 + T - 1) / T, T>>>((const float4*)w_k1, (float4*)wt_k1, n4);
        round_tf32_kernel<<<(n4 + T - 1) / T, T>>>((const float4*)w_k2, (float4*)wt_k2, n4);
        round_tf32_kernel<<<(n4 + T - 1) / T, T>>>((const float4*)w_v1, (float4*)wt_v1, n4);
        round_tf32_kernel<<<(n4 + T - 1) / T, T>>>((const float4*)w_v2, (float4*)wt_v2, n4);
        n4 = (int)(3 * MW / 4);
        round_tf32_kernel<<<(n4 + T - 1) / T, T>>>((const float4*)in_w, (float4*)wt_in, n4);
        n4 = (int)(MW / 4);
        round_tf32_kernel<<<(n4 + T - 1) / T, T>>>((const float4*)out_w, (float4*)wt_out, n4);
    }

    const dim3 blk(256);
    const dim3 gBig(8, M_BIG / BM);    // (8, 288)
    const dim3 gSm(8, M_SMALL / BM);   // (8, 72)

    // K path
    gemm_tf32<1, 1><<<gBig, blk, smem_bytes>>>(xfr, wt_k1, b_k1, h);
    gemm_tf32<0, 0><<<gBig, blk, smem_bytes>>>(h, wt_k2, b_k2, key);
    ln_kernel<<<M_BIG, 256>>>(key, ln_k_w, ln_k_b);
    // V path
    gemm_tf32<1, 1><<<gBig, blk, smem_bytes>>>(xfr, wt_v1, b_v1, h);
    gemm_tf32<0, 0><<<gBig, blk, smem_bytes>>>(h, wt_v2, b_v2, val);
    ln_kernel<<<M_BIG, 256>>>(val, ln_v_w, ln_v_b);
    // Q path
    gemm_tf32<0, 0><<<gSm, blk, smem_bytes>>>(xr, wt_q, nullptr, qb);
    ln_kernel<<<M_SMALL, 256>>>(qb, ln_q_w, ln_q_b);
    // in_proj
    gemm_tf32<0, 1><<<gSm,  blk, smem_bytes>>>(qb,  wt_in,          in_b,        qh);
    gemm_tf32<0, 1><<<gBig, blk, smem_bytes>>>(key, wt_in + MW,     in_b + 1024, kh);
    gemm_tf32<0, 1><<<gBig, blk, smem_bytes>>>(val, wt_in + 2 * MW, in_b + 2048, vh);
    // attention
    attn_kernel<<<M_SMALL, 256>>>(qh, kh, vh, o);
    // out_proj -> d_out
    gemm_tf32<0, 0><<<gSm, blk, smem_bytes>>>(o, wt_out, out_b, (float*)d_out);
}

// round 5
// speedup vs baseline: 1.7112x; 1.6791x over previous
#include <cuda_runtime.h>
#include <cuda_fp16.h>
#include <cstdint>
#include <math.h>

// ---------------------------------------------------------------------------
// TokenPacker R5: fp16 mma.sync m16n8k16 (2x FLOP per HMMA vs tf32 k8, same
// 10-bit mantissa precision), fp16 operands/intermediates (halves all memory
// traffic), fp32 accumulation everywhere. 128x128 tile, 16 warps/SM,
// 4-stage cp.async.
// ---------------------------------------------------------------------------

#define E_DIM   1024
#define N_IMG   64
#define NQ_TOK  144
#define TN_TOK  576
#define M_BIG   (N_IMG * TN_TOK)   // 36864
#define M_SMALL (N_IMG * NQ_TOK)   // 9216
#define NKT     64                 // K / 16
#define STAGES  4
#define SROW_B  80                 // smem row pitch bytes (40 halves) - conflict-free
#define STAGE_B (256 * SROW_B)     // 128 A rows + 128 B rows = 20480
#define BM      128
#define BN      128

// Scratch (device statics; no cudaMalloc allowed) - fp16
__device__ __align__(256) __half g_h  [(size_t)M_BIG   * E_DIM];
__device__ __align__(256) __half g_key[(size_t)M_BIG   * E_DIM];
__device__ __align__(256) __half g_val[(size_t)M_BIG   * E_DIM];
__device__ __align__(256) __half g_kh [(size_t)M_BIG   * E_DIM];
__device__ __align__(256) __half g_vh [(size_t)M_BIG   * E_DIM];
__device__ __align__(256) __half g_q  [(size_t)M_SMALL * E_DIM];
__device__ __align__(256) __half g_qh [(size_t)M_SMALL * E_DIM];
__device__ __align__(256) __half g_o  [(size_t)M_SMALL * E_DIM];
__device__ __align__(256) __half g_xr [(size_t)M_SMALL * E_DIM];
__device__ __align__(256) __half g_xfr[(size_t)M_BIG   * E_DIM];
__device__ __align__(256) __half g_wt [9ull * 1024 * 1024];

__device__ __forceinline__ float gelu_exact(float x) {
    return 0.5f * x * (1.0f + erff(x * 0.70710678118654752f));
}

#define CP_ASYNC16(smem_u32a, gptr) \
    asm volatile("cp.async.cg.shared.global [%0], [%1], 16;\n" :: "r"(smem_u32a), "l"(gptr))

// ---------------------------------------------------------------------------
// f32 -> f16 conversion prepass: 4 floats -> 4 halves per thread
// ---------------------------------------------------------------------------
__global__ void to_half_kernel(const float4* __restrict__ in,
                               __half2* __restrict__ out, int n4)
{
    int i = blockIdx.x * blockDim.x + threadIdx.x;
    if (i < n4) {
        float4 v = in[i];
        out[2 * i]     = __floats2half2_rn(v.x, v.y);
        out[2 * i + 1] = __floats2half2_rn(v.z, v.w);
    }
}

// ---------------------------------------------------------------------------
// GEMM: C[M x 1024] = act(A[M x 1024] @ W[1024 x 1024]^T + bias)
// A, W fp16. ACT: 0=none 1=GELU. OUTF: 0 = half output, 1 = float output.
// 128x128 tile, 256 threads, 8 warps of 64x32, mma.sync.m16n8k16.f16,
// 4-stage cp.async. M % 128 == 0, N = K = 1024.
// ---------------------------------------------------------------------------
template <int ACT, int OUTF>
__global__ __launch_bounds__(256, 2)
void gemm_f16(const __half* __restrict__ A, const __half* __restrict__ W,
              const float* __restrict__ bias, void* __restrict__ Cv)
{
    extern __shared__ __align__(128) char smem[];
    // per stage: A rows [0,128) then B rows [128,256), each row SROW_B bytes
    uint32_t sb;
    asm("{ .reg .u64 t; cvta.to.shared.u64 t, %1; cvt.u32.u64 %0, t; }" : "=r"(sb) : "l"(smem));

    const int tid  = threadIdx.x;
    const int warp = tid >> 5;
    const int lane = tid & 31;
    const int grp  = lane >> 2;   // 0..7
    const int tig  = lane & 3;    // 0..3
    const int wm   = (warp & 1) * 64;
    const int wn   = (warp >> 1) * 32;
    const int row0 = blockIdx.y * BM;
    const int col0 = blockIdx.x * BN;

    float acc[4][4][4];
    #pragma unroll
    for (int i = 0; i < 4; i++)
        #pragma unroll
        for (int j = 0; j < 4; j++)
            #pragma unroll
            for (int k = 0; k < 4; k++) acc[i][j][k] = 0.0f;

    // gmem->smem: per stage, per matrix: 128 rows x 32B; 256 threads do 1 op each
    const int fr = tid >> 1;            // row 0..127
    const int fc = (tid & 1) * 16;      // byte chunk 0 / 16
    const __half* Abase = A + (size_t)(row0 + fr) * E_DIM + fc / 2;
    const __half* Wbase = W + (size_t)(col0 + fr) * E_DIM + fc / 2;
    const uint32_t a_dst = sb + fr * SROW_B + fc;
    const uint32_t b_dst = sb + (128 + fr) * SROW_B + fc;

    #pragma unroll
    for (int kt = 0; kt < 3; kt++) {
        CP_ASYNC16(a_dst + kt * STAGE_B, Abase + kt * 16);
        CP_ASYNC16(b_dst + kt * STAGE_B, Wbase + kt * 16);
        asm volatile("cp.async.commit_group;\n");
    }

    for (int kt = 0; kt < NKT; kt++) {
        asm volatile("cp.async.wait_group 2;\n");
        __syncthreads();

        const int pf = kt + 3;
        if (pf < NKT) {
            const int s = pf & 3;
            CP_ASYNC16(a_dst + s * STAGE_B, Abase + pf * 16);
            CP_ASYNC16(b_dst + s * STAGE_B, Wbase + pf * 16);
        }
        asm volatile("cp.async.commit_group;\n");

        const uint32_t abase = sb + (kt & 3) * STAGE_B;
        const uint32_t bbase = abase + 128 * SROW_B;

        // fragments: A half2 at [row][2*tig + {0,8}], B half2 at [col][2*tig + {0,8}]
        uint32_t af[4][4], bf[4][2];
        #pragma unroll
        for (int mi = 0; mi < 4; mi++) {
            const int r = wm + mi * 16 + grp;
            const uint32_t a0 = abase + r * SROW_B + tig * 4;
            const uint32_t a1 = abase + (r + 8) * SROW_B + tig * 4;
            asm volatile("ld.shared.b32 %0, [%1];" : "=r"(af[mi][0]) : "r"(a0));
            asm volatile("ld.shared.b32 %0, [%1];" : "=r"(af[mi][1]) : "r"(a1));
            asm volatile("ld.shared.b32 %0, [%1];" : "=r"(af[mi][2]) : "r"(a0 + 16));
            asm volatile("ld.shared.b32 %0, [%1];" : "=r"(af[mi][3]) : "r"(a1 + 16));
        }
        #pragma unroll
        for (int ni = 0; ni < 4; ni++) {
            const int c = wn + ni * 8 + grp;
            const uint32_t b0 = bbase + c * SROW_B + tig * 4;
            asm volatile("ld.shared.b32 %0, [%1];" : "=r"(bf[ni][0]) : "r"(b0));
            asm volatile("ld.shared.b32 %0, [%1];" : "=r"(bf[ni][1]) : "r"(b0 + 16));
        }
        #pragma unroll
        for (int mi = 0; mi < 4; mi++)
            #pragma unroll
            for (int ni = 0; ni < 4; ni++)
                asm volatile(
                    "mma.sync.aligned.m16n8k16.row.col.f32.f16.f16.f32 "
                    "{%0,%1,%2,%3}, {%4,%5,%6,%7}, {%8,%9}, {%0,%1,%2,%3};\n"
                    : "+f"(acc[mi][ni][0]), "+f"(acc[mi][ni][1]),
                      "+f"(acc[mi][ni][2]), "+f"(acc[mi][ni][3])
                    : "r"(af[mi][0]), "r"(af[mi][1]), "r"(af[mi][2]), "r"(af[mi][3]),
                      "r"(bf[ni][0]), "r"(bf[ni][1]));
    }

    // epilogue: bias + activation, store half2 (or float2 for final output)
    #pragma unroll
    for (int ni = 0; ni < 4; ni++) {
        const int col = col0 + wn + ni * 8 + tig * 2;
        float bv0 = 0.0f, bv1 = 0.0f;
        if (bias) { bv0 = bias[col]; bv1 = bias[col + 1]; }
        #pragma unroll
        for (int mi = 0; mi < 4; mi++) {
            #pragma unroll
            for (int half_ = 0; half_ < 2; half_++) {
                const int row = row0 + wm + mi * 16 + grp + half_ * 8;
                float v0 = acc[mi][ni][half_ * 2 + 0] + bv0;
                float v1 = acc[mi][ni][half_ * 2 + 1] + bv1;
                if (ACT == 1) { v0 = gelu_exact(v0); v1 = gelu_exact(v1); }
                if (OUTF) {
                    *(float2*)((float*)Cv + (size_t)row * E_DIM + col) = make_float2(v0, v1);
                } else {
                    *(__half2*)((__half*)Cv + (size_t)row * E_DIM + col) = __floats2half2_rn(v0, v1);
                }
            }
        }
    }
}

// ---------------------------------------------------------------------------
// In-place LayerNorm over rows of 1024 halves (eps=1e-6), fp32 math.
// ---------------------------------------------------------------------------
__global__ void ln_kernel(__half* __restrict__ data,
                          const float* __restrict__ w, const float* __restrict__ b)
{
    const int row = blockIdx.x;
    __half2* p = (__half2*)(data + (size_t)row * E_DIM);
    const __half2 h0 = p[2 * threadIdx.x], h1 = p[2 * threadIdx.x + 1];
    float2 f0 = __half22float2(h0), f1 = __half22float2(h1);
    float s = f0.x + f0.y + f1.x + f1.y;
    float q = f0.x * f0.x + f0.y * f0.y + f1.x * f1.x + f1.y * f1.y;
    #pragma unroll
    for (int o = 16; o; o >>= 1) {
        s += __shfl_xor_sync(0xffffffffu, s, o);
        q += __shfl_xor_sync(0xffffffffu, q, o);
    }
    __shared__ float ss[8], sq[8];
    const int warp = threadIdx.x >> 5, lane = threadIdx.x & 31;
    if (lane == 0) { ss[warp] = s; sq[warp] = q; }
    __syncthreads();
    if (warp == 0) {
        s = (lane < 8) ? ss[lane] : 0.0f;
        q = (lane < 8) ? sq[lane] : 0.0f;
        #pragma unroll
        for (int o = 4; o; o >>= 1) {
            s += __shfl_xor_sync(0xffffffffu, s, o);
            q += __shfl_xor_sync(0xffffffffu, q, o);
        }
        if (lane == 0) { ss[0] = s; sq[0] = q; }
    }
    __syncthreads();
    const float mean = ss[0] * (1.0f / 1024.0f);
    const float var  = sq[0] * (1.0f / 1024.0f) - mean * mean;
    const float rstd = rsqrtf(var + 1e-6f);
    const float4 wv = ((const float4*)w)[threadIdx.x];
    const float4 bv = ((const float4*)b)[threadIdx.x];
    p[2 * threadIdx.x] = __floats2half2_rn((f0.x - mean) * rstd * wv.x + bv.x,
                                           (f0.y - mean) * rstd * wv.y + bv.y);
    p[2 * threadIdx.x + 1] = __floats2half2_rn((f1.x - mean) * rstd * wv.z + bv.z,
                                               (f1.y - mean) * rstd * wv.w + bv.w);
}

// ---------------------------------------------------------------------------
// Attention: q len 1 over its 2x2 key patch. fp16 in/out, fp32 math.
// ---------------------------------------------------------------------------
__global__ void attn_kernel(const __half* __restrict__ qh, const __half* __restrict__ kh,
                            const __half* __restrict__ vh, __half* __restrict__ o)
{
    const int r  = blockIdx.x;
    const int n  = r / NQ_TOK;
    const int qi = r - n * NQ_TOK;
    const int ar = qi / 12;
    const int ac = qi - ar * 12;
    const int head = threadIdx.x >> 5, lane = threadIdx.x & 31;
    const size_t qoff = (size_t)r * E_DIM + head * 128 + lane * 4;
    const __half2* qp = (const __half2*)(qh + qoff);
    const float2 q0 = __half22float2(qp[0]), q1 = __half22float2(qp[1]);

    int trow[4];
    #pragma unroll
    for (int j = 0; j < 4; j++)
        trow[j] = n * TN_TOK + (2 * ar + (j >> 1)) * 24 + (2 * ac + (j & 1));

    float s[4];
    #pragma unroll
    for (int j = 0; j < 4; j++) {
        const __half2* kp = (const __half2*)(kh + (size_t)trow[j] * E_DIM + head * 128 + lane * 4);
        const float2 k0 = __half22float2(kp[0]), k1 = __half22float2(kp[1]);
        float d = q0.x * k0.x + q0.y * k0.y + q1.x * k1.x + q1.y * k1.y;
        #pragma unroll
        for (int off = 16; off; off >>= 1) d += __shfl_xor_sync(0xffffffffu, d, off);
        s[j] = d * 0.08838834764831843f;   // 1/sqrt(128)
    }
    const float m = fmaxf(fmaxf(s[0], s[1]), fmaxf(s[2], s[3]));
    float e[4], tot = 0.0f;
    #pragma unroll
    for (int j = 0; j < 4; j++) { e[j] = expf(s[j] - m); tot += e[j]; }
    const float inv = 1.0f / tot;

    float a0 = 0.f, a1 = 0.f, a2 = 0.f, a3 = 0.f;
    #pragma unroll
    for (int j = 0; j < 4; j++) {
        const float pj = e[j] * inv;
        const __half2* vp = (const __half2*)(vh + (size_t)trow[j] * E_DIM + head * 128 + lane * 4);
        const float2 v0 = __half22float2(vp[0]), v1 = __half22float2(vp[1]);
        a0 += pj * v0.x; a1 += pj * v0.y; a2 += pj * v1.x; a3 += pj * v1.y;
    }
    __half2* op = (__half2*)(o + qoff);
    op[0] = __floats2half2_rn(a0, a1);
    op[1] = __floats2half2_rn(a2, a3);
}

// ---------------------------------------------------------------------------
extern "C" void kernel_launch(void* const* d_in, const int* in_sizes, int n_in,
                              void* d_out, int out_size)
{
    const float* x      = (const float*)d_in[0];
    const float* x_feat = (const float*)d_in[1];
    const float* w_q    = (const float*)d_in[2];
    const float* w_k1   = (const float*)d_in[3];
    const float* b_k1   = (const float*)d_in[4];
    const float* w_k2   = (const float*)d_in[5];
    const float* b_k2   = (const float*)d_in[6];
    const float* w_v1   = (const float*)d_in[7];
    const float* b_v1   = (const float*)d_in[8];
    const float* w_v2   = (const float*)d_in[9];
    const float* b_v2   = (const float*)d_in[10];
    const float* ln_q_w = (const float*)d_in[11];
    const float* ln_q_b = (const float*)d_in[12];
    const float* ln_k_w = (const float*)d_in[13];
    const float* ln_k_b = (const float*)d_in[14];
    const float* ln_v_w = (const float*)d_in[15];
    const float* ln_v_b = (const float*)d_in[16];
    const float* in_w   = (const float*)d_in[17];
    const float* in_b   = (const float*)d_in[18];
    const float* out_w  = (const float*)d_in[19];
    const float* out_b  = (const float*)d_in[20];

    __half *h, *key, *val, *kh, *vh, *qb, *qh, *o, *xr, *xfr, *wt;
    cudaGetSymbolAddress((void**)&h,   g_h);
    cudaGetSymbolAddress((void**)&key, g_key);
    cudaGetSymbolAddress((void**)&val, g_val);
    cudaGetSymbolAddress((void**)&kh,  g_kh);
    cudaGetSymbolAddress((void**)&vh,  g_vh);
    cudaGetSymbolAddress((void**)&qb,  g_q);
    cudaGetSymbolAddress((void**)&qh,  g_qh);
    cudaGetSymbolAddress((void**)&o,   g_o);
    cudaGetSymbolAddress((void**)&xr,  g_xr);
    cudaGetSymbolAddress((void**)&xfr, g_xfr);
    cudaGetSymbolAddress((void**)&wt,  g_wt);

    const size_t MW = 1024ull * 1024ull;
    __half* wt_q   = wt;
    __half* wt_k1  = wt + 1 * MW;
    __half* wt_k2  = wt + 2 * MW;
    __half* wt_v1  = wt + 3 * MW;
    __half* wt_v2  = wt + 4 * MW;
    __half* wt_in  = wt + 5 * MW;   // 3 MW
    __half* wt_out = wt + 8 * MW;

    const int smem_bytes = STAGES * STAGE_B;  // 81920
    cudaFuncSetAttribute(gemm_f16<0, 0>, cudaFuncAttributeMaxDynamicSharedMemorySize, smem_bytes);
    cudaFuncSetAttribute(gemm_f16<1, 0>, cudaFuncAttributeMaxDynamicSharedMemorySize, smem_bytes);
    cudaFuncSetAttribute(gemm_f16<0, 1>, cudaFuncAttributeMaxDynamicSharedMemorySize, smem_bytes);

    // prepass: convert inputs + weights to fp16
    {
        const int T = 256;
        int n4;
        n4 = M_SMALL * E_DIM / 4;
        to_half_kernel<<<(n4 + T - 1) / T, T>>>((const float4*)x, (__half2*)xr, n4);
        n4 = M_BIG * E_DIM / 4;
        to_half_kernel<<<(n4 + T - 1) / T, T>>>((const float4*)x_feat, (__half2*)xfr, n4);
        n4 = (int)(MW / 4);
        to_half_kernel<<<(n4 + T - 1) / T, T>>>((const float4*)w_q,  (__half2*)wt_q,  n4);
        to_half_kernel<<<(n4 + T - 1) / T, T>>>((const float4*)w_k1, (__half2*)wt_k1, n4);
        to_half_kernel<<<(n4 + T - 1) / T, T>>>((const float4*)w_k2, (__half2*)wt_k2, n4);
        to_half_kernel<<<(n4 + T - 1) / T, T>>>((const float4*)w_v1, (__half2*)wt_v1, n4);
        to_half_kernel<<<(n4 + T - 1) / T, T>>>((const float4*)w_v2, (__half2*)wt_v2, n4);
        n4 = (int)(3 * MW / 4);
        to_half_kernel<<<(n4 + T - 1) / T, T>>>((const float4*)in_w, (__half2*)wt_in, n4);
        n4 = (int)(MW / 4);
        to_half_kernel<<<(n4 + T - 1) / T, T>>>((const float4*)out_w, (__half2*)wt_out, n4);
    }

    const dim3 blk(256);
    const dim3 gBig(8, M_BIG / BM);    // (8, 288)
    const dim3 gSm(8, M_SMALL / BM);   // (8, 72)

    // K path
    gemm_f16<1, 0><<<gBig, blk, smem_bytes>>>(xfr, wt_k1, b_k1, h);
    gemm_f16<0, 0><<<gBig, blk, smem_bytes>>>(h, wt_k2, b_k2, key);
    ln_kernel<<<M_BIG, 256>>>(key, ln_k_w, ln_k_b);
    // V path
    gemm_f16<1, 0><<<gBig, blk, smem_bytes>>>(xfr, wt_v1, b_v1, h);
    gemm_f16<0, 0><<<gBig, blk, smem_bytes>>>(h, wt_v2, b_v2, val);
    ln_kernel<<<M_BIG, 256>>>(val, ln_v_w, ln_v_b);
    // Q path
    gemm_f16<0, 0><<<gSm, blk, smem_bytes>>>(xr, wt_q, nullptr, qb);
    ln_kernel<<<M_SMALL, 256>>>(qb, ln_q_w, ln_q_b);
    // in_proj
    gemm_f16<0, 0><<<gSm,  blk, smem_bytes>>>(qb,  wt_in,          in_b,        qh);
    gemm_f16<0, 0><<<gBig, blk, smem_bytes>>>(key, wt_in + MW,     in_b + 1024, kh);
    gemm_f16<0, 0><<<gBig, blk, smem_bytes>>>(val, wt_in + 2 * MW, in_b + 2048, vh);
    // attention
    attn_kernel<<<M_SMALL, 256>>>(qh, kh, vh, o);
    // out_proj -> d_out (float)
    gemm_f16<0, 1><<<gSm, blk, smem_bytes>>>(o, wt_out, out_b, d_out);
}

// round 6
// speedup vs baseline: 1.7223x; 1.0065x over previous
#include <cuda_runtime.h>
#include <cuda_fp16.h>
#include <cstdint>
#include <math.h>

// ---------------------------------------------------------------------------
// TokenPacker R6: fp16 m16n8k16, CTA tile 256x128, 8 warps of 64x64 (cuts
// smem fragment duplication: A x2, B x4-on-half -> smem 256 cyc = HMMA 256
// cyc per slab, vs R5's smem-bound 384). Single merged prepass kernel (also
// aligns ncu -s 5 capture onto a big GEMM). fp32 accumulation throughout.
// ---------------------------------------------------------------------------

#define E_DIM   1024
#define N_IMG   64
#define NQ_TOK  144
#define TN_TOK  576
#define M_BIG   (N_IMG * TN_TOK)   // 36864
#define M_SMALL (N_IMG * NQ_TOK)   // 9216
#define NKT     64                 // K / 16
#define STAGES  4
#define SROW_B  80                 // smem row pitch bytes (32B payload + pad)
#define BM      256
#define BN      128
#define STAGE_B ((BM + BN) * SROW_B)   // 30720

// Scratch (device statics; no cudaMalloc allowed) - fp16
__device__ __align__(256) __half g_h  [(size_t)M_BIG   * E_DIM];
__device__ __align__(256) __half g_key[(size_t)M_BIG   * E_DIM];
__device__ __align__(256) __half g_val[(size_t)M_BIG   * E_DIM];
__device__ __align__(256) __half g_kh [(size_t)M_BIG   * E_DIM];
__device__ __align__(256) __half g_vh [(size_t)M_BIG   * E_DIM];
__device__ __align__(256) __half g_q  [(size_t)M_SMALL * E_DIM];
__device__ __align__(256) __half g_qh [(size_t)M_SMALL * E_DIM];
__device__ __align__(256) __half g_o  [(size_t)M_SMALL * E_DIM];
__device__ __align__(256) __half g_xr [(size_t)M_SMALL * E_DIM];
__device__ __align__(256) __half g_xfr[(size_t)M_BIG   * E_DIM];
__device__ __align__(256) __half g_wt [9ull * 1024 * 1024];

__device__ __forceinline__ float gelu_exact(float x) {
    return 0.5f * x * (1.0f + erff(x * 0.70710678118654752f));
}

#define CP_ASYNC16(smem_u32a, gptr) \
    asm volatile("cp.async.cg.shared.global [%0], [%1], 16;\n" :: "r"(smem_u32a), "l"(gptr))

// ---------------------------------------------------------------------------
// Merged f32 -> f16 conversion prepass (one launch, 9 jobs)
// ---------------------------------------------------------------------------
struct ConvJob { const float4* src; __half2* dst; int n4; };
struct ConvJobs { ConvJob j[9]; };

__global__ void conv_all_kernel(ConvJobs jobs)
{
    const ConvJob jb = jobs.j[blockIdx.y];
    for (int i = blockIdx.x * blockDim.x + threadIdx.x; i < jb.n4;
         i += gridDim.x * blockDim.x) {
        float4 v = jb.src[i];
        jb.dst[2 * i]     = __floats2half2_rn(v.x, v.y);
        jb.dst[2 * i + 1] = __floats2half2_rn(v.z, v.w);
    }
}

// ---------------------------------------------------------------------------
// GEMM: C[M x 1024] = act(A[M x 1024] @ W[1024 x 1024]^T + bias)
// A, W fp16. ACT: 0=none 1=GELU. OUTF: 0 = half out, 1 = float out.
// 256x128 tile, 256 threads, 8 warps of 64x64 (4x2), mma.sync.m16n8k16,
// 4-stage cp.async. M % 256 == 0, N = K = 1024.
// ---------------------------------------------------------------------------
template <int ACT, int OUTF>
__global__ __launch_bounds__(256, 1)
void gemm_f16(const __half* __restrict__ A, const __half* __restrict__ W,
              const float* __restrict__ bias, void* __restrict__ Cv)
{
    extern __shared__ __align__(128) char smem[];
    // per stage: A rows [0,256) then B rows [256,384), each row SROW_B bytes
    uint32_t sb;
    asm("{ .reg .u64 t; cvta.to.shared.u64 t, %1; cvt.u32.u64 %0, t; }" : "=r"(sb) : "l"(smem));

    const int tid  = threadIdx.x;
    const int warp = tid >> 5;
    const int lane = tid & 31;
    const int grp  = lane >> 2;   // 0..7
    const int tig  = lane & 3;    // 0..3
    const int wm   = (warp & 3) * 64;   // 4 m-groups
    const int wn   = (warp >> 2) * 64;  // 2 n-groups
    const int row0 = blockIdx.y * BM;
    const int col0 = blockIdx.x * BN;

    float acc[4][8][4];
    #pragma unroll
    for (int i = 0; i < 4; i++)
        #pragma unroll
        for (int j = 0; j < 8; j++)
            #pragma unroll
            for (int k = 0; k < 4; k++) acc[i][j][k] = 0.0f;

    // gmem->smem per stage: A 256 rows x 32B (2 ops/thread), B 128 rows x 32B (1 op)
    const int fr = tid >> 1;            // 0..127
    const int fc = (tid & 1) * 16;      // byte chunk 0/16
    const __half* Abase = A + (size_t)(row0 + fr) * E_DIM + fc / 2;
    const __half* A2base = Abase + (size_t)128 * E_DIM;
    const __half* Wbase = W + (size_t)(col0 + fr) * E_DIM + fc / 2;
    const uint32_t a_dst  = sb + fr * SROW_B + fc;
    const uint32_t a2_dst = sb + (128 + fr) * SROW_B + fc;
    const uint32_t b_dst  = sb + (BM + fr) * SROW_B + fc;

    #pragma unroll
    for (int kt = 0; kt < 3; kt++) {
        CP_ASYNC16(a_dst  + kt * STAGE_B, Abase  + kt * 16);
        CP_ASYNC16(a2_dst + kt * STAGE_B, A2base + kt * 16);
        CP_ASYNC16(b_dst  + kt * STAGE_B, Wbase  + kt * 16);
        asm volatile("cp.async.commit_group;\n");
    }

    for (int kt = 0; kt < NKT; kt++) {
        asm volatile("cp.async.wait_group 2;\n");
        __syncthreads();

        const int pf = kt + 3;
        if (pf < NKT) {
            const int s = pf & 3;
            CP_ASYNC16(a_dst  + s * STAGE_B, Abase  + pf * 16);
            CP_ASYNC16(a2_dst + s * STAGE_B, A2base + pf * 16);
            CP_ASYNC16(b_dst  + s * STAGE_B, Wbase  + pf * 16);
        }
        asm volatile("cp.async.commit_group;\n");

        const uint32_t abase = sb + (kt & 3) * STAGE_B;
        const uint32_t bbase = abase + BM * SROW_B;

        uint32_t af[4][4], bf[8][2];
        #pragma unroll
        for (int mi = 0; mi < 4; mi++) {
            const int r = wm + mi * 16 + grp;
            const uint32_t a0 = abase + r * SROW_B + tig * 4;
            const uint32_t a1 = abase + (r + 8) * SROW_B + tig * 4;
            asm volatile("ld.shared.b32 %0, [%1];" : "=r"(af[mi][0]) : "r"(a0));
            asm volatile("ld.shared.b32 %0, [%1];" : "=r"(af[mi][1]) : "r"(a1));
            asm volatile("ld.shared.b32 %0, [%1];" : "=r"(af[mi][2]) : "r"(a0 + 16));
            asm volatile("ld.shared.b32 %0, [%1];" : "=r"(af[mi][3]) : "r"(a1 + 16));
        }
        #pragma unroll
        for (int ni = 0; ni < 8; ni++) {
            const int c = wn + ni * 8 + grp;
            const uint32_t b0 = bbase + c * SROW_B + tig * 4;
            asm volatile("ld.shared.b32 %0, [%1];" : "=r"(bf[ni][0]) : "r"(b0));
            asm volatile("ld.shared.b32 %0, [%1];" : "=r"(bf[ni][1]) : "r"(b0 + 16));
        }
        #pragma unroll
        for (int mi = 0; mi < 4; mi++)
            #pragma unroll
            for (int ni = 0; ni < 8; ni++)
                asm volatile(
                    "mma.sync.aligned.m16n8k16.row.col.f32.f16.f16.f32 "
                    "{%0,%1,%2,%3}, {%4,%5,%6,%7}, {%8,%9}, {%0,%1,%2,%3};\n"
                    : "+f"(acc[mi][ni][0]), "+f"(acc[mi][ni][1]),
                      "+f"(acc[mi][ni][2]), "+f"(acc[mi][ni][3])
                    : "r"(af[mi][0]), "r"(af[mi][1]), "r"(af[mi][2]), "r"(af[mi][3]),
                      "r"(bf[ni][0]), "r"(bf[ni][1]));
    }

    // epilogue
    #pragma unroll
    for (int ni = 0; ni < 8; ni++) {
        const int col = col0 + wn + ni * 8 + tig * 2;
        float bv0 = 0.0f, bv1 = 0.0f;
        if (bias) { bv0 = bias[col]; bv1 = bias[col + 1]; }
        #pragma unroll
        for (int mi = 0; mi < 4; mi++) {
            #pragma unroll
            for (int half_ = 0; half_ < 2; half_++) {
                const int row = row0 + wm + mi * 16 + grp + half_ * 8;
                float v0 = acc[mi][ni][half_ * 2 + 0] + bv0;
                float v1 = acc[mi][ni][half_ * 2 + 1] + bv1;
                if (ACT == 1) { v0 = gelu_exact(v0); v1 = gelu_exact(v1); }
                if (OUTF) {
                    *(float2*)((float*)Cv + (size_t)row * E_DIM + col) = make_float2(v0, v1);
                } else {
                    *(__half2*)((__half*)Cv + (size_t)row * E_DIM + col) = __floats2half2_rn(v0, v1);
                }
            }
        }
    }
}

// ---------------------------------------------------------------------------
// In-place LayerNorm over rows of 1024 halves (eps=1e-6), fp32 math.
// ---------------------------------------------------------------------------
__global__ void ln_kernel(__half* __restrict__ data,
                          const float* __restrict__ w, const float* __restrict__ b)
{
    const int row = blockIdx.x;
    __half2* p = (__half2*)(data + (size_t)row * E_DIM);
    const __half2 h0 = p[2 * threadIdx.x], h1 = p[2 * threadIdx.x + 1];
    float2 f0 = __half22float2(h0), f1 = __half22float2(h1);
    float s = f0.x + f0.y + f1.x + f1.y;
    float q = f0.x * f0.x + f0.y * f0.y + f1.x * f1.x + f1.y * f1.y;
    #pragma unroll
    for (int o = 16; o; o >>= 1) {
        s += __shfl_xor_sync(0xffffffffu, s, o);
        q += __shfl_xor_sync(0xffffffffu, q, o);
    }
    __shared__ float ss[8], sq[8];
    const int warp = threadIdx.x >> 5, lane = threadIdx.x & 31;
    if (lane == 0) { ss[warp] = s; sq[warp] = q; }
    __syncthreads();
    if (warp == 0) {
        s = (lane < 8) ? ss[lane] : 0.0f;
        q = (lane < 8) ? sq[lane] : 0.0f;
        #pragma unroll
        for (int o = 4; o; o >>= 1) {
            s += __shfl_xor_sync(0xffffffffu, s, o);
            q += __shfl_xor_sync(0xffffffffu, q, o);
        }
        if (lane == 0) { ss[0] = s; sq[0] = q; }
    }
    __syncthreads();
    const float mean = ss[0] * (1.0f / 1024.0f);
    const float var  = sq[0] * (1.0f / 1024.0f) - mean * mean;
    const float rstd = rsqrtf(var + 1e-6f);
    const float4 wv = ((const float4*)w)[threadIdx.x];
    const float4 bv = ((const float4*)b)[threadIdx.x];
    p[2 * threadIdx.x] = __floats2half2_rn((f0.x - mean) * rstd * wv.x + bv.x,
                                           (f0.y - mean) * rstd * wv.y + bv.y);
    p[2 * threadIdx.x + 1] = __floats2half2_rn((f1.x - mean) * rstd * wv.z + bv.z,
                                               (f1.y - mean) * rstd * wv.w + bv.w);
}

// ---------------------------------------------------------------------------
// Attention: q len 1 over its 2x2 key patch. fp16 in/out, fp32 math.
// ---------------------------------------------------------------------------
__global__ void attn_kernel(const __half* __restrict__ qh, const __half* __restrict__ kh,
                            const __half* __restrict__ vh, __half* __restrict__ o)
{
    const int r  = blockIdx.x;
    const int n  = r / NQ_TOK;
    const int qi = r - n * NQ_TOK;
    const int ar = qi / 12;
    const int ac = qi - ar * 12;
    const int head = threadIdx.x >> 5, lane = threadIdx.x & 31;
    const size_t qoff = (size_t)r * E_DIM + head * 128 + lane * 4;
    const __half2* qp = (const __half2*)(qh + qoff);
    const float2 q0 = __half22float2(qp[0]), q1 = __half22float2(qp[1]);

    int trow[4];
    #pragma unroll
    for (int j = 0; j < 4; j++)
        trow[j] = n * TN_TOK + (2 * ar + (j >> 1)) * 24 + (2 * ac + (j & 1));

    float s[4];
    #pragma unroll
    for (int j = 0; j < 4; j++) {
        const __half2* kp = (const __half2*)(kh + (size_t)trow[j] * E_DIM + head * 128 + lane * 4);
        const float2 k0 = __half22float2(kp[0]), k1 = __half22float2(kp[1]);
        float d = q0.x * k0.x + q0.y * k0.y + q1.x * k1.x + q1.y * k1.y;
        #pragma unroll
        for (int off = 16; off; off >>= 1) d += __shfl_xor_sync(0xffffffffu, d, off);
        s[j] = d * 0.08838834764831843f;   // 1/sqrt(128)
    }
    const float m = fmaxf(fmaxf(s[0], s[1]), fmaxf(s[2], s[3]));
    float e[4], tot = 0.0f;
    #pragma unroll
    for (int j = 0; j < 4; j++) { e[j] = expf(s[j] - m); tot += e[j]; }
    const float inv = 1.0f / tot;

    float a0 = 0.f, a1 = 0.f, a2 = 0.f, a3 = 0.f;
    #pragma unroll
    for (int j = 0; j < 4; j++) {
        const float pj = e[j] * inv;
        const __half2* vp = (const __half2*)(vh + (size_t)trow[j] * E_DIM + head * 128 + lane * 4);
        const float2 v0 = __half22float2(vp[0]), v1 = __half22float2(vp[1]);
        a0 += pj * v0.x; a1 += pj * v0.y; a2 += pj * v1.x; a3 += pj * v1.y;
    }
    __half2* op = (__half2*)(o + qoff);
    op[0] = __floats2half2_rn(a0, a1);
    op[1] = __floats2half2_rn(a2, a3);
}

// ---------------------------------------------------------------------------
extern "C" void kernel_launch(void* const* d_in, const int* in_sizes, int n_in,
                              void* d_out, int out_size)
{
    const float* x      = (const float*)d_in[0];
    const float* x_feat = (const float*)d_in[1];
    const float* w_q    = (const float*)d_in[2];
    const float* w_k1   = (const float*)d_in[3];
    const float* b_k1   = (const float*)d_in[4];
    const float* w_k2   = (const float*)d_in[5];
    const float* b_k2   = (const float*)d_in[6];
    const float* w_v1   = (const float*)d_in[7];
    const float* b_v1   = (const float*)d_in[8];
    const float* w_v2   = (const float*)d_in[9];
    const float* b_v2   = (const float*)d_in[10];
    const float* ln_q_w = (const float*)d_in[11];
    const float* ln_q_b = (const float*)d_in[12];
    const float* ln_k_w = (const float*)d_in[13];
    const float* ln_k_b = (const float*)d_in[14];
    const float* ln_v_w = (const float*)d_in[15];
    const float* ln_v_b = (const float*)d_in[16];
    const float* in_w   = (const float*)d_in[17];
    const float* in_b   = (const float*)d_in[18];
    const float* out_w  = (const float*)d_in[19];
    const float* out_b  = (const float*)d_in[20];

    __half *h, *key, *val, *kh, *vh, *qb, *qh, *o, *xr, *xfr, *wt;
    cudaGetSymbolAddress((void**)&h,   g_h);
    cudaGetSymbolAddress((void**)&key, g_key);
    cudaGetSymbolAddress((void**)&val, g_val);
    cudaGetSymbolAddress((void**)&kh,  g_kh);
    cudaGetSymbolAddress((void**)&vh,  g_vh);
    cudaGetSymbolAddress((void**)&qb,  g_q);
    cudaGetSymbolAddress((void**)&qh,  g_qh);
    cudaGetSymbolAddress((void**)&o,   g_o);
    cudaGetSymbolAddress((void**)&xr,  g_xr);
    cudaGetSymbolAddress((void**)&xfr, g_xfr);
    cudaGetSymbolAddress((void**)&wt,  g_wt);

    const size_t MW = 1024ull * 1024ull;
    __half* wt_q   = wt;
    __half* wt_k1  = wt + 1 * MW;
    __half* wt_k2  = wt + 2 * MW;
    __half* wt_v1  = wt + 3 * MW;
    __half* wt_v2  = wt + 4 * MW;
    __half* wt_in  = wt + 5 * MW;   // 3 MW
    __half* wt_out = wt + 8 * MW;

    const int smem_bytes = STAGES * STAGE_B;  // 122880
    cudaFuncSetAttribute(gemm_f16<0, 0>, cudaFuncAttributeMaxDynamicSharedMemorySize, smem_bytes);
    cudaFuncSetAttribute(gemm_f16<1, 0>, cudaFuncAttributeMaxDynamicSharedMemorySize, smem_bytes);
    cudaFuncSetAttribute(gemm_f16<0, 1>, cudaFuncAttributeMaxDynamicSharedMemorySize, smem_bytes);

    // single merged prepass launch (launch #1)
    {
        ConvJobs jobs;
        jobs.j[0] = { (const float4*)x,      (__half2*)xr,     M_SMALL * E_DIM / 4 };
        jobs.j[1] = { (const float4*)x_feat, (__half2*)xfr,    M_BIG   * E_DIM / 4 };
        jobs.j[2] = { (const float4*)w_q,    (__half2*)wt_q,   (int)(MW / 4) };
        jobs.j[3] = { (const float4*)w_k1,   (__half2*)wt_k1,  (int)(MW / 4) };
        jobs.j[4] = { (const float4*)w_k2,   (__half2*)wt_k2,  (int)(MW / 4) };
        jobs.j[5] = { (const float4*)w_v1,   (__half2*)wt_v1,  (int)(MW / 4) };
        jobs.j[6] = { (const float4*)w_v2,   (__half2*)wt_v2,  (int)(MW / 4) };
        jobs.j[7] = { (const float4*)in_w,   (__half2*)wt_in,  (int)(3 * MW / 4) };
        jobs.j[8] = { (const float4*)out_w,  (__half2*)wt_out, (int)(MW / 4) };
        conv_all_kernel<<<dim3(1024, 9), 256>>>(jobs);
    }

    const dim3 blk(256);
    const dim3 gBig(8, M_BIG / BM);    // (8, 144)
    const dim3 gSm(8, M_SMALL / BM);   // (8, 36)

    // K path (launches 2,3,4)
    gemm_f16<1, 0><<<gBig, blk, smem_bytes>>>(xfr, wt_k1, b_k1, h);
    gemm_f16<0, 0><<<gBig, blk, smem_bytes>>>(h, wt_k2, b_k2, key);
    ln_kernel<<<M_BIG, 256>>>(key, ln_k_w, ln_k_b);
    // V path (launches 5,6 <- ncu -s 5 captures launch 6 = big GEMM)
    gemm_f16<1, 0><<<gBig, blk, smem_bytes>>>(xfr, wt_v1, b_v1, h);
    gemm_f16<0, 0><<<gBig, blk, smem_bytes>>>(h, wt_v2, b_v2, val);
    ln_kernel<<<M_BIG, 256>>>(val, ln_v_w, ln_v_b);
    // Q path
    gemm_f16<0, 0><<<gSm, blk, smem_bytes>>>(xr, wt_q, nullptr, qb);
    ln_kernel<<<M_SMALL, 256>>>(qb, ln_q_w, ln_q_b);
    // in_proj
    gemm_f16<0, 0><<<gSm,  blk, smem_bytes>>>(qb,  wt_in,          in_b,        qh);
    gemm_f16<0, 0><<<gBig, blk, smem_bytes>>>(key, wt_in + MW,     in_b + 1024, kh);
    gemm_f16<0, 0><<<gBig, blk, smem_bytes>>>(val, wt_in + 2 * MW, in_b + 2048, vh);
    // attention
    attn_kernel<<<M_SMALL, 256>>>(qh, kh, vh, o);
    // out_proj -> d_out (float)
    gemm_f16<0, 1><<<gSm, blk, smem_bytes>>>(o, wt_out, out_b, d_out);
}

// round 7
// speedup vs baseline: 2.0186x; 1.1720x over previous
#include <cuda_runtime.h>
#include <cuda_fp16.h>
#include <cstdint>
#include <math.h>

// ---------------------------------------------------------------------------
// TokenPacker R7: fp16 m16n8k16 GEMM with ldmatrix.x4 fragment loads (40 vs
// 64 issues/kt), merged K1+V1 GEMM (N=2048, shared A), launch order tuned so
// ncu's captured slot (my 4th launch) is a plain big GEMM.
// Model: sm_100 legacy tensor path is MAC-rate-capped (~266 TF/s); goal is
// maximizing pipe-active fraction (R5/R6 at ~83%).
// ---------------------------------------------------------------------------

#define E_DIM   1024
#define N_IMG   64
#define NQ_TOK  144
#define TN_TOK  576
#define M_BIG   (N_IMG * TN_TOK)   // 36864
#define M_SMALL (N_IMG * NQ_TOK)   // 9216
#define NKT     64                 // K / 16
#define STAGES  4
#define SROW_B  80                 // smem row pitch bytes (32B payload + pad)
#define BM      128
#define BN      128
#define STAGE_B ((BM + BN) * SROW_B)   // 20480

// Scratch (device statics; no cudaMalloc allowed)
__device__ __align__(256) __half g_h2 [(size_t)M_BIG * 2048];   // merged gelu(K1|V1)
__device__ __align__(256) __half g_key[(size_t)M_BIG   * E_DIM];
__device__ __align__(256) __half g_val[(size_t)M_BIG   * E_DIM];
__device__ __align__(256) __half g_kh [(size_t)M_BIG   * E_DIM];
__device__ __align__(256) __half g_vh [(size_t)M_BIG   * E_DIM];
__device__ __align__(256) __half g_q  [(size_t)M_SMALL * E_DIM];
__device__ __align__(256) __half g_qh [(size_t)M_SMALL * E_DIM];
__device__ __align__(256) __half g_o  [(size_t)M_SMALL * E_DIM];
__device__ __align__(256) __half g_xr [(size_t)M_SMALL * E_DIM];
__device__ __align__(256) __half g_xfr[(size_t)M_BIG   * E_DIM];
__device__ __align__(256) __half g_wt [9ull * 1024 * 1024];
__device__ __align__(256) float  g_bcat[2048];                  // [b_k1; b_v1]

__device__ __forceinline__ float gelu_exact(float x) {
    return 0.5f * x * (1.0f + erff(x * 0.70710678118654752f));
}

#define CP_ASYNC16(smem_u32a, gptr) \
    asm volatile("cp.async.cg.shared.global [%0], [%1], 16;\n" :: "r"(smem_u32a), "l"(gptr))

#define LDSM_X4(r0, r1, r2, r3, addr) \
    asm volatile("ldmatrix.sync.aligned.m8n8.x4.shared.b16 {%0,%1,%2,%3}, [%4];" \
                 : "=r"(r0), "=r"(r1), "=r"(r2), "=r"(r3) : "r"(addr))

// ---------------------------------------------------------------------------
// Merged f32 -> f16 conversion prepass (one launch, 9 jobs)
// ---------------------------------------------------------------------------
struct ConvJob { const float4* src; __half2* dst; int n4; };
struct ConvJobs { ConvJob j[9]; };

__global__ void conv_all_kernel(ConvJobs jobs)
{
    const ConvJob jb = jobs.j[blockIdx.y];
    for (int i = blockIdx.x * blockDim.x + threadIdx.x; i < jb.n4;
         i += gridDim.x * blockDim.x) {
        float4 v = jb.src[i];
        jb.dst[2 * i]     = __floats2half2_rn(v.x, v.y);
        jb.dst[2 * i + 1] = __floats2half2_rn(v.z, v.w);
    }
}

__global__ void bias_concat_kernel(const float* __restrict__ b0,
                                   const float* __restrict__ b1,
                                   float* __restrict__ out)
{
    int i = blockIdx.x * blockDim.x + threadIdx.x;   // 0..2047
    out[i] = (i < 1024) ? b0[i] : b1[i - 1024];
}

// ---------------------------------------------------------------------------
// GEMM: C[M x N] = act(A[M x K=1024] @ W[N x 1024]^T + bias)
// A row stride = lda, C row stride = ldc. 128x128 tile, 8 warps of 64x32,
// mma.sync.m16n8k16 with ldmatrix.x4 fragments, 4-stage cp.async.
// ---------------------------------------------------------------------------
template <int ACT, int OUTF>
__global__ __launch_bounds__(256, 2)
void gemm_f16(const __half* __restrict__ A, int lda,
              const __half* __restrict__ W,
              const float* __restrict__ bias,
              void* __restrict__ Cv, int ldc)
{
    extern __shared__ __align__(128) char smem[];
    uint32_t sb;
    asm("{ .reg .u64 t; cvta.to.shared.u64 t, %1; cvt.u32.u64 %0, t; }" : "=r"(sb) : "l"(smem));

    const int tid  = threadIdx.x;
    const int warp = tid >> 5;
    const int lane = tid & 31;
    const int grp  = lane >> 2;
    const int tig  = lane & 3;
    const int wm   = (warp & 1) * 64;
    const int wn   = (warp >> 1) * 32;
    const int row0 = blockIdx.y * BM;
    const int col0 = blockIdx.x * BN;

    float acc[4][4][4];
    #pragma unroll
    for (int i = 0; i < 4; i++)
        #pragma unroll
        for (int j = 0; j < 4; j++)
            #pragma unroll
            for (int k = 0; k < 4; k++) acc[i][j][k] = 0.0f;

    // ldmatrix per-lane offsets (within a stage)
    const int lg  = lane >> 3;          // 0..3 (matrix group)
    const int lr8 = lane & 7;           // row within 8
    // A mats: {r0-7 k0, r8-15 k0, r0-7 k8, r8-15 k8}
    uint32_t aoff[4];
    #pragma unroll
    for (int mi = 0; mi < 4; mi++)
        aoff[mi] = (uint32_t)((wm + mi * 16 + (lg & 1) * 8 + lr8) * SROW_B + (lg >> 1) * 16);
    // B mats (pair of n-tiles j, j+1): {nj k0, nj k8, nj+1 k0, nj+1 k8}
    uint32_t boff[2];
    #pragma unroll
    for (int jj = 0; jj < 2; jj++)
        boff[jj] = (uint32_t)((BM + wn + (jj * 2 + (lg >> 1)) * 8 + lr8) * SROW_B + (lg & 1) * 16);

    // gmem->smem: A 128 rows x 32B, B 128 rows x 32B; 1 op each per thread
    const int fr = tid >> 1;
    const int fc = (tid & 1) * 16;
    const __half* Abase = A + (size_t)(row0 + fr) * lda + fc / 2;
    const __half* Wbase = W + (size_t)(col0 + fr) * E_DIM + fc / 2;
    const uint32_t a_dst = sb + fr * SROW_B + fc;
    const uint32_t b_dst = sb + (BM + fr) * SROW_B + fc;

    #pragma unroll
    for (int kt = 0; kt < 3; kt++) {
        CP_ASYNC16(a_dst + kt * STAGE_B, Abase + kt * 16);
        CP_ASYNC16(b_dst + kt * STAGE_B, Wbase + kt * 16);
        asm volatile("cp.async.commit_group;\n");
    }

    for (int kt = 0; kt < NKT; kt++) {
        asm volatile("cp.async.wait_group 2;\n");
        __syncthreads();

        const int pf = kt + 3;
        if (pf < NKT) {
            const int s = pf & 3;
            CP_ASYNC16(a_dst + s * STAGE_B, Abase + pf * 16);
            CP_ASYNC16(b_dst + s * STAGE_B, Wbase + pf * 16);
        }
        asm volatile("cp.async.commit_group;\n");

        const uint32_t stage = sb + (kt & 3) * STAGE_B;

        uint32_t af[4][4], bf[4][2];
        #pragma unroll
        for (int mi = 0; mi < 4; mi++)
            LDSM_X4(af[mi][0], af[mi][1], af[mi][2], af[mi][3], stage + aoff[mi]);
        #pragma unroll
        for (int jj = 0; jj < 2; jj++)
            LDSM_X4(bf[jj * 2][0], bf[jj * 2][1], bf[jj * 2 + 1][0], bf[jj * 2 + 1][1],
                    stage + boff[jj]);

        #pragma unroll
        for (int mi = 0; mi < 4; mi++)
            #pragma unroll
            for (int ni = 0; ni < 4; ni++)
                asm volatile(
                    "mma.sync.aligned.m16n8k16.row.col.f32.f16.f16.f32 "
                    "{%0,%1,%2,%3}, {%4,%5,%6,%7}, {%8,%9}, {%0,%1,%2,%3};\n"
                    : "+f"(acc[mi][ni][0]), "+f"(acc[mi][ni][1]),
                      "+f"(acc[mi][ni][2]), "+f"(acc[mi][ni][3])
                    : "r"(af[mi][0]), "r"(af[mi][1]), "r"(af[mi][2]), "r"(af[mi][3]),
                      "r"(bf[ni][0]), "r"(bf[ni][1]));
    }

    // epilogue
    #pragma unroll
    for (int ni = 0; ni < 4; ni++) {
        const int col = col0 + wn + ni * 8 + tig * 2;
        float bv0 = 0.0f, bv1 = 0.0f;
        if (bias) { bv0 = bias[col]; bv1 = bias[col + 1]; }
        #pragma unroll
        for (int mi = 0; mi < 4; mi++) {
            #pragma unroll
            for (int half_ = 0; half_ < 2; half_++) {
                const int row = row0 + wm + mi * 16 + grp + half_ * 8;
                float v0 = acc[mi][ni][half_ * 2 + 0] + bv0;
                float v1 = acc[mi][ni][half_ * 2 + 1] + bv1;
                if (ACT == 1) { v0 = gelu_exact(v0); v1 = gelu_exact(v1); }
                if (OUTF) {
                    *(float2*)((float*)Cv + (size_t)row * ldc + col) = make_float2(v0, v1);
                } else {
                    *(__half2*)((__half*)Cv + (size_t)row * ldc + col) = __floats2half2_rn(v0, v1);
                }
            }
        }
    }
}

// ---------------------------------------------------------------------------
// In-place LayerNorm over rows of 1024 halves (eps=1e-6), fp32 math.
// ---------------------------------------------------------------------------
__global__ void ln_kernel(__half* __restrict__ data,
                          const float* __restrict__ w, const float* __restrict__ b)
{
    const int row = blockIdx.x;
    __half2* p = (__half2*)(data + (size_t)row * E_DIM);
    const __half2 h0 = p[2 * threadIdx.x], h1 = p[2 * threadIdx.x + 1];
    float2 f0 = __half22float2(h0), f1 = __half22float2(h1);
    float s = f0.x + f0.y + f1.x + f1.y;
    float q = f0.x * f0.x + f0.y * f0.y + f1.x * f1.x + f1.y * f1.y;
    #pragma unroll
    for (int o = 16; o; o >>= 1) {
        s += __shfl_xor_sync(0xffffffffu, s, o);
        q += __shfl_xor_sync(0xffffffffu, q, o);
    }
    __shared__ float ss[8], sq[8];
    const int warp = threadIdx.x >> 5, lane = threadIdx.x & 31;
    if (lane == 0) { ss[warp] = s; sq[warp] = q; }
    __syncthreads();
    if (warp == 0) {
        s = (lane < 8) ? ss[lane] : 0.0f;
        q = (lane < 8) ? sq[lane] : 0.0f;
        #pragma unroll
        for (int o = 4; o; o >>= 1) {
            s += __shfl_xor_sync(0xffffffffu, s, o);
            q += __shfl_xor_sync(0xffffffffu, q, o);
        }
        if (lane == 0) { ss[0] = s; sq[0] = q; }
    }
    __syncthreads();
    const float mean = ss[0] * (1.0f / 1024.0f);
    const float var  = sq[0] * (1.0f / 1024.0f) - mean * mean;
    const float rstd = rsqrtf(var + 1e-6f);
    const float4 wv = ((const float4*)w)[threadIdx.x];
    const float4 bv = ((const float4*)b)[threadIdx.x];
    p[2 * threadIdx.x] = __floats2half2_rn((f0.x - mean) * rstd * wv.x + bv.x,
                                           (f0.y - mean) * rstd * wv.y + bv.y);
    p[2 * threadIdx.x + 1] = __floats2half2_rn((f1.x - mean) * rstd * wv.z + bv.z,
                                               (f1.y - mean) * rstd * wv.w + bv.w);
}

// ---------------------------------------------------------------------------
// Attention: q len 1 over its 2x2 key patch. fp16 in/out, fp32 math.
// ---------------------------------------------------------------------------
__global__ void attn_kernel(const __half* __restrict__ qh, const __half* __restrict__ kh,
                            const __half* __restrict__ vh, __half* __restrict__ o)
{
    const int r  = blockIdx.x;
    const int n  = r / NQ_TOK;
    const int qi = r - n * NQ_TOK;
    const int ar = qi / 12;
    const int ac = qi - ar * 12;
    const int head = threadIdx.x >> 5, lane = threadIdx.x & 31;
    const size_t qoff = (size_t)r * E_DIM + head * 128 + lane * 4;
    const __half2* qp = (const __half2*)(qh + qoff);
    const float2 q0 = __half22float2(qp[0]), q1 = __half22float2(qp[1]);

    int trow[4];
    #pragma unroll
    for (int j = 0; j < 4; j++)
        trow[j] = n * TN_TOK + (2 * ar + (j >> 1)) * 24 + (2 * ac + (j & 1));

    float s[4];
    #pragma unroll
    for (int j = 0; j < 4; j++) {
        const __half2* kp = (const __half2*)(kh + (size_t)trow[j] * E_DIM + head * 128 + lane * 4);
        const float2 k0 = __half22float2(kp[0]), k1 = __half22float2(kp[1]);
        float d = q0.x * k0.x + q0.y * k0.y + q1.x * k1.x + q1.y * k1.y;
        #pragma unroll
        for (int off = 16; off; off >>= 1) d += __shfl_xor_sync(0xffffffffu, d, off);
        s[j] = d * 0.08838834764831843f;   // 1/sqrt(128)
    }
    const float m = fmaxf(fmaxf(s[0], s[1]), fmaxf(s[2], s[3]));
    float e[4], tot = 0.0f;
    #pragma unroll
    for (int j = 0; j < 4; j++) { e[j] = expf(s[j] - m); tot += e[j]; }
    const float inv = 1.0f / tot;

    float a0 = 0.f, a1 = 0.f, a2 = 0.f, a3 = 0.f;
    #pragma unroll
    for (int j = 0; j < 4; j++) {
        const float pj = e[j] * inv;
        const __half2* vp = (const __half2*)(vh + (size_t)trow[j] * E_DIM + head * 128 + lane * 4);
        const float2 v0 = __half22float2(vp[0]), v1 = __half22float2(vp[1]);
        a0 += pj * v0.x; a1 += pj * v0.y; a2 += pj * v1.x; a3 += pj * v1.y;
    }
    __half2* op = (__half2*)(o + qoff);
    op[0] = __floats2half2_rn(a0, a1);
    op[1] = __floats2half2_rn(a2, a3);
}

// ---------------------------------------------------------------------------
extern "C" void kernel_launch(void* const* d_in, const int* in_sizes, int n_in,
                              void* d_out, int out_size)
{
    const float* x      = (const float*)d_in[0];
    const float* x_feat = (const float*)d_in[1];
    const float* w_q    = (const float*)d_in[2];
    const float* w_k1   = (const float*)d_in[3];
    const float* b_k1   = (const float*)d_in[4];
    const float* w_k2   = (const float*)d_in[5];
    const float* b_k2   = (const float*)d_in[6];
    const float* w_v1   = (const float*)d_in[7];
    const float* b_v1   = (const float*)d_in[8];
    const float* w_v2   = (const float*)d_in[9];
    const float* b_v2   = (const float*)d_in[10];
    const float* ln_q_w = (const float*)d_in[11];
    const float* ln_q_b = (const float*)d_in[12];
    const float* ln_k_w = (const float*)d_in[13];
    const float* ln_k_b = (const float*)d_in[14];
    const float* ln_v_w = (const float*)d_in[15];
    const float* ln_v_b = (const float*)d_in[16];
    const float* in_w   = (const float*)d_in[17];
    const float* in_b   = (const float*)d_in[18];
    const float* out_w  = (const float*)d_in[19];
    const float* out_b  = (const float*)d_in[20];

    __half *h2, *key, *val, *kh, *vh, *qb, *qh, *o, *xr, *xfr, *wt;
    float* bcat;
    cudaGetSymbolAddress((void**)&h2,  g_h2);
    cudaGetSymbolAddress((void**)&key, g_key);
    cudaGetSymbolAddress((void**)&val, g_val);
    cudaGetSymbolAddress((void**)&kh,  g_kh);
    cudaGetSymbolAddress((void**)&vh,  g_vh);
    cudaGetSymbolAddress((void**)&qb,  g_q);
    cudaGetSymbolAddress((void**)&qh,  g_qh);
    cudaGetSymbolAddress((void**)&o,   g_o);
    cudaGetSymbolAddress((void**)&xr,  g_xr);
    cudaGetSymbolAddress((void**)&xfr, g_xfr);
    cudaGetSymbolAddress((void**)&wt,  g_wt);
    cudaGetSymbolAddress((void**)&bcat, g_bcat);

    const size_t MW = 1024ull * 1024ull;
    __half* wt_kv1 = wt;                 // [w_k1 ; w_v1] -> 2048 rows x 1024
    __half* wt_k2  = wt + 2 * MW;
    __half* wt_v2  = wt + 3 * MW;
    __half* wt_q   = wt + 4 * MW;
    __half* wt_in  = wt + 5 * MW;        // 3 MW
    __half* wt_out = wt + 8 * MW;

    const int smem_bytes = STAGES * STAGE_B;  // 81920
    cudaFuncSetAttribute(gemm_f16<0, 0>, cudaFuncAttributeMaxDynamicSharedMemorySize, smem_bytes);
    cudaFuncSetAttribute(gemm_f16<1, 0>, cudaFuncAttributeMaxDynamicSharedMemorySize, smem_bytes);
    cudaFuncSetAttribute(gemm_f16<0, 1>, cudaFuncAttributeMaxDynamicSharedMemorySize, smem_bytes);

    // launch 1: merged conversion prepass
    {
        ConvJobs jobs;
        jobs.j[0] = { (const float4*)x,      (__half2*)xr,      M_SMALL * E_DIM / 4 };
        jobs.j[1] = { (const float4*)x_feat, (__half2*)xfr,     M_BIG   * E_DIM / 4 };
        jobs.j[2] = { (const float4*)w_k1,   (__half2*)wt_kv1,  (int)(MW / 4) };
        jobs.j[3] = { (const float4*)w_v1,   (__half2*)(wt_kv1 + MW), (int)(MW / 4) };
        jobs.j[4] = { (const float4*)w_k2,   (__half2*)wt_k2,   (int)(MW / 4) };
        jobs.j[5] = { (const float4*)w_v2,   (__half2*)wt_v2,   (int)(MW / 4) };
        jobs.j[6] = { (const float4*)w_q,    (__half2*)wt_q,    (int)(MW / 4) };
        jobs.j[7] = { (const float4*)in_w,   (__half2*)wt_in,   (int)(3 * MW / 4) };
        jobs.j[8] = { (const float4*)out_w,  (__half2*)wt_out,  (int)(MW / 4) };
        conv_all_kernel<<<dim3(1024, 9), 256>>>(jobs);
    }
    // launch 2: bias concat
    bias_concat_kernel<<<8, 256>>>(b_k1, b_v1, bcat);

    const dim3 blk(256);
    const dim3 gKV(16, M_BIG / BM);    // N=2048
    const dim3 gBig(8, M_BIG / BM);
    const dim3 gSm(8, M_SMALL / BM);

    // launch 3: merged K1+V1 (gelu) -> h2 [M_BIG x 2048]
    gemm_f16<1, 0><<<gKV, blk, smem_bytes>>>(xfr, E_DIM, wt_kv1, bcat, h2, 2048);
    // launch 4 (ncu capture slot): K2
    gemm_f16<0, 0><<<gBig, blk, smem_bytes>>>(h2, 2048, wt_k2, b_k2, key, E_DIM);
    // launch 5: V2
    gemm_f16<0, 0><<<gBig, blk, smem_bytes>>>(h2 + 1024, 2048, wt_v2, b_v2, val, E_DIM);
    // LNs
    ln_kernel<<<M_BIG, 256>>>(key, ln_k_w, ln_k_b);
    ln_kernel<<<M_BIG, 256>>>(val, ln_v_w, ln_v_b);
    // Q path
    gemm_f16<0, 0><<<gSm, blk, smem_bytes>>>(xr, E_DIM, wt_q, nullptr, qb, E_DIM);
    ln_kernel<<<M_SMALL, 256>>>(qb, ln_q_w, ln_q_b);
    // in_proj
    gemm_f16<0, 0><<<gSm,  blk, smem_bytes>>>(qb,  E_DIM, wt_in,          in_b,        qh, E_DIM);
    gemm_f16<0, 0><<<gBig, blk, smem_bytes>>>(key, E_DIM, wt_in + MW,     in_b + 1024, kh, E_DIM);
    gemm_f16<0, 0><<<gBig, blk, smem_bytes>>>(val, E_DIM, wt_in + 2 * MW, in_b + 2048, vh, E_DIM);
    // attention
    attn_kernel<<<M_SMALL, 256>>>(qh, kh, vh, o);
    // out_proj -> d_out (float)
    gemm_f16<0, 1><<<gSm, blk, smem_bytes>>>(o, E_DIM, wt_out, out_b, d_out, E_DIM);
}

// round 8
// speedup vs baseline: 2.2303x; 1.1049x over previous
#include <cuda_runtime.h>
#include <cuda_fp16.h>
#include <cstdint>
#include <math.h>

// ---------------------------------------------------------------------------
// TokenPacker R8: K=32 pipeline stages (half the barriers of R7) with
// intra-stage chunk fragment double-buffering (chunk1 ldmatrix in flight
// under chunk0 MMAs). fp16 m16n8k16, 128x128 CTA tile, 8 warps of 64x32,
// 4-stage cp.async. Calibration from R7 profile: fp16 HMMA ceiling ~560 TF/s,
// R7 GEMM at 48% pipe-active; this round attacks duty cycle.
// ---------------------------------------------------------------------------

#define E_DIM   1024
#define N_IMG   64
#define NQ_TOK  144
#define TN_TOK  576
#define M_BIG   (N_IMG * TN_TOK)   // 36864
#define M_SMALL (N_IMG * NQ_TOK)   // 9216
#define NST     32                 // K / 32 stages
#define STAGES  4
#define SROW_B  80                 // pitch bytes (64B payload + 16 pad)
#define BM      128
#define BN      128
#define STAGE_B ((BM + BN) * SROW_B)   // 20480

// Scratch (device statics; no cudaMalloc allowed)
__device__ __align__(256) __half g_h2 [(size_t)M_BIG * 2048];   // gelu(K1|V1)
__device__ __align__(256) __half g_key[(size_t)M_BIG   * E_DIM];
__device__ __align__(256) __half g_val[(size_t)M_BIG   * E_DIM];
__device__ __align__(256) __half g_kh [(size_t)M_BIG   * E_DIM];
__device__ __align__(256) __half g_vh [(size_t)M_BIG   * E_DIM];
__device__ __align__(256) __half g_q  [(size_t)M_SMALL * E_DIM];
__device__ __align__(256) __half g_qh [(size_t)M_SMALL * E_DIM];
__device__ __align__(256) __half g_o  [(size_t)M_SMALL * E_DIM];
__device__ __align__(256) __half g_xr [(size_t)M_SMALL * E_DIM];
__device__ __align__(256) __half g_xfr[(size_t)M_BIG   * E_DIM];
__device__ __align__(256) __half g_wt [9ull * 1024 * 1024];
__device__ __align__(256) float  g_bcat[2048];

__device__ __forceinline__ float gelu_exact(float x) {
    return 0.5f * x * (1.0f + erff(x * 0.70710678118654752f));
}

#define CP_ASYNC16(smem_u32a, gptr) \
    asm volatile("cp.async.cg.shared.global [%0], [%1], 16;\n" :: "r"(smem_u32a), "l"(gptr))

#define LDSM_X4(r0, r1, r2, r3, addr) \
    asm volatile("ldmatrix.sync.aligned.m8n8.x4.shared.b16 {%0,%1,%2,%3}, [%4];" \
                 : "=r"(r0), "=r"(r1), "=r"(r2), "=r"(r3) : "r"(addr))

#define MMA16816(d, a, b) \
    asm volatile("mma.sync.aligned.m16n8k16.row.col.f32.f16.f16.f32 " \
                 "{%0,%1,%2,%3}, {%4,%5,%6,%7}, {%8,%9}, {%0,%1,%2,%3};\n" \
                 : "+f"((d)[0]), "+f"((d)[1]), "+f"((d)[2]), "+f"((d)[3]) \
                 : "r"((a)[0]), "r"((a)[1]), "r"((a)[2]), "r"((a)[3]), \
                   "r"((b)[0]), "r"((b)[1]))

// ---------------------------------------------------------------------------
// Merged f32 -> f16 conversion prepass
// ---------------------------------------------------------------------------
struct ConvJob { const float4* src; __half2* dst; int n4; };
struct ConvJobs { ConvJob j[9]; };

__global__ void conv_all_kernel(ConvJobs jobs)
{
    const ConvJob jb = jobs.j[blockIdx.y];
    for (int i = blockIdx.x * blockDim.x + threadIdx.x; i < jb.n4;
         i += gridDim.x * blockDim.x) {
        float4 v = jb.src[i];
        jb.dst[2 * i]     = __floats2half2_rn(v.x, v.y);
        jb.dst[2 * i + 1] = __floats2half2_rn(v.z, v.w);
    }
}

__global__ void bias_concat_kernel(const float* __restrict__ b0,
                                   const float* __restrict__ b1,
                                   float* __restrict__ out)
{
    int i = blockIdx.x * blockDim.x + threadIdx.x;
    out[i] = (i < 1024) ? b0[i] : b1[i - 1024];
}

// ---------------------------------------------------------------------------
// GEMM: C[M x N] = act(A[M x K=1024] @ W[N x 1024]^T + bias)
// ---------------------------------------------------------------------------
template <int ACT, int OUTF>
__global__ __launch_bounds__(256, 2)
void gemm_f16(const __half* __restrict__ A, int lda,
              const __half* __restrict__ W,
              const float* __restrict__ bias,
              void* __restrict__ Cv, int ldc)
{
    extern __shared__ __align__(128) char smem[];
    uint32_t sb;
    asm("{ .reg .u64 t; cvta.to.shared.u64 t, %1; cvt.u32.u64 %0, t; }" : "=r"(sb) : "l"(smem));

    const int tid  = threadIdx.x;
    const int warp = tid >> 5;
    const int lane = tid & 31;
    const int grp  = lane >> 2;
    const int tig  = lane & 3;
    const int wm   = (warp & 1) * 64;
    const int wn   = (warp >> 1) * 32;
    const int row0 = blockIdx.y * BM;
    const int col0 = blockIdx.x * BN;

    float acc[4][4][4];
    #pragma unroll
    for (int i = 0; i < 4; i++)
        #pragma unroll
        for (int j = 0; j < 4; j++)
            #pragma unroll
            for (int k = 0; k < 4; k++) acc[i][j][k] = 0.0f;

    // ldmatrix lane offsets (chunk 0; chunk 1 = +32 bytes)
    const int lg  = lane >> 3;
    const int lr8 = lane & 7;
    uint32_t aoff[4];
    #pragma unroll
    for (int mi = 0; mi < 4; mi++)
        aoff[mi] = (uint32_t)((wm + mi * 16 + (lg & 1) * 8 + lr8) * SROW_B + (lg >> 1) * 16);
    uint32_t boff[2];
    #pragma unroll
    for (int jj = 0; jj < 2; jj++)
        boff[jj] = (uint32_t)((BM + wn + (jj * 2 + (lg >> 1)) * 8 + lr8) * SROW_B + (lg & 1) * 16);

    // gmem->smem: per stage per matrix 128 rows x 64B = 512 x 16B tasks,
    // 2 tasks/thread (rows fr0, fr0+64)
    const int fr0 = tid >> 2;
    const int fc  = (tid & 3) * 16;   // bytes
    const __half* Ag0 = A + (size_t)(row0 + fr0) * lda + fc / 2;
    const __half* Ag1 = Ag0 + (size_t)64 * lda;
    const __half* Wg0 = W + (size_t)(col0 + fr0) * E_DIM + fc / 2;
    const __half* Wg1 = Wg0 + (size_t)64 * E_DIM;
    const uint32_t aD0 = sb + fr0 * SROW_B + fc;
    const uint32_t aD1 = aD0 + 64 * SROW_B;
    const uint32_t bD0 = sb + (BM + fr0) * SROW_B + fc;
    const uint32_t bD1 = bD0 + 64 * SROW_B;

    #pragma unroll
    for (int st = 0; st < 3; st++) {
        const int ko = st * 32;   // halves
        CP_ASYNC16(aD0 + st * STAGE_B, Ag0 + ko);
        CP_ASYNC16(aD1 + st * STAGE_B, Ag1 + ko);
        CP_ASYNC16(bD0 + st * STAGE_B, Wg0 + ko);
        CP_ASYNC16(bD1 + st * STAGE_B, Wg1 + ko);
        asm volatile("cp.async.commit_group;\n");
    }

    for (int i = 0; i < NST; i++) {
        asm volatile("cp.async.wait_group 2;\n");
        __syncthreads();

        const int pf = i + 3;
        if (pf < NST) {
            const int s = pf & 3;
            const int ko = pf * 32;
            CP_ASYNC16(aD0 + s * STAGE_B, Ag0 + ko);
            CP_ASYNC16(aD1 + s * STAGE_B, Ag1 + ko);
            CP_ASYNC16(bD0 + s * STAGE_B, Wg0 + ko);
            CP_ASYNC16(bD1 + s * STAGE_B, Wg1 + ko);
        }
        asm volatile("cp.async.commit_group;\n");

        const uint32_t stage = sb + (i & 3) * STAGE_B;

        uint32_t af0[4][4], bf0[4][2], af1[4][4], bf1[4][2];
        // chunk 0 fragments
        #pragma unroll
        for (int mi = 0; mi < 4; mi++)
            LDSM_X4(af0[mi][0], af0[mi][1], af0[mi][2], af0[mi][3], stage + aoff[mi]);
        #pragma unroll
        for (int jj = 0; jj < 2; jj++)
            LDSM_X4(bf0[jj * 2][0], bf0[jj * 2][1], bf0[jj * 2 + 1][0], bf0[jj * 2 + 1][1],
                    stage + boff[jj]);
        // chunk 1 fragments (in flight under chunk 0 MMAs)
        #pragma unroll
        for (int mi = 0; mi < 4; mi++)
            LDSM_X4(af1[mi][0], af1[mi][1], af1[mi][2], af1[mi][3], stage + aoff[mi] + 32);
        #pragma unroll
        for (int jj = 0; jj < 2; jj++)
            LDSM_X4(bf1[jj * 2][0], bf1[jj * 2][1], bf1[jj * 2 + 1][0], bf1[jj * 2 + 1][1],
                    stage + boff[jj] + 32);

        #pragma unroll
        for (int mi = 0; mi < 4; mi++)
            #pragma unroll
            for (int ni = 0; ni < 4; ni++)
                MMA16816(acc[mi][ni], af0[mi], bf0[ni]);
        #pragma unroll
        for (int mi = 0; mi < 4; mi++)
            #pragma unroll
            for (int ni = 0; ni < 4; ni++)
                MMA16816(acc[mi][ni], af1[mi], bf1[ni]);
    }

    // epilogue
    #pragma unroll
    for (int ni = 0; ni < 4; ni++) {
        const int col = col0 + wn + ni * 8 + tig * 2;
        float bv0 = 0.0f, bv1 = 0.0f;
        if (bias) { bv0 = bias[col]; bv1 = bias[col + 1]; }
        #pragma unroll
        for (int mi = 0; mi < 4; mi++) {
            #pragma unroll
            for (int half_ = 0; half_ < 2; half_++) {
                const int row = row0 + wm + mi * 16 + grp + half_ * 8;
                float v0 = acc[mi][ni][half_ * 2 + 0] + bv0;
                float v1 = acc[mi][ni][half_ * 2 + 1] + bv1;
                if (ACT == 1) { v0 = gelu_exact(v0); v1 = gelu_exact(v1); }
                if (OUTF) {
                    *(float2*)((float*)Cv + (size_t)row * ldc + col) = make_float2(v0, v1);
                } else {
                    *(__half2*)((__half*)Cv + (size_t)row * ldc + col) = __floats2half2_rn(v0, v1);
                }
            }
        }
    }
}

// ---------------------------------------------------------------------------
// In-place LayerNorm (rows of 1024 halves, eps=1e-6, fp32 math)
// ---------------------------------------------------------------------------
__global__ void ln_kernel(__half* __restrict__ data,
                          const float* __restrict__ w, const float* __restrict__ b)
{
    const int row = blockIdx.x;
    __half2* p = (__half2*)(data + (size_t)row * E_DIM);
    const __half2 h0 = p[2 * threadIdx.x], h1 = p[2 * threadIdx.x + 1];
    float2 f0 = __half22float2(h0), f1 = __half22float2(h1);
    float s = f0.x + f0.y + f1.x + f1.y;
    float q = f0.x * f0.x + f0.y * f0.y + f1.x * f1.x + f1.y * f1.y;
    #pragma unroll
    for (int o = 16; o; o >>= 1) {
        s += __shfl_xor_sync(0xffffffffu, s, o);
        q += __shfl_xor_sync(0xffffffffu, q, o);
    }
    __shared__ float ss[8], sq[8];
    const int warp = threadIdx.x >> 5, lane = threadIdx.x & 31;
    if (lane == 0) { ss[warp] = s; sq[warp] = q; }
    __syncthreads();
    if (warp == 0) {
        s = (lane < 8) ? ss[lane] : 0.0f;
        q = (lane < 8) ? sq[lane] : 0.0f;
        #pragma unroll
        for (int o = 4; o; o >>= 1) {
            s += __shfl_xor_sync(0xffffffffu, s, o);
            q += __shfl_xor_sync(0xffffffffu, q, o);
        }
        if (lane == 0) { ss[0] = s; sq[0] = q; }
    }
    __syncthreads();
    const float mean = ss[0] * (1.0f / 1024.0f);
    const float var  = sq[0] * (1.0f / 1024.0f) - mean * mean;
    const float rstd = rsqrtf(var + 1e-6f);
    const float4 wv = ((const float4*)w)[threadIdx.x];
    const float4 bv = ((const float4*)b)[threadIdx.x];
    p[2 * threadIdx.x] = __floats2half2_rn((f0.x - mean) * rstd * wv.x + bv.x,
                                           (f0.y - mean) * rstd * wv.y + bv.y);
    p[2 * threadIdx.x + 1] = __floats2half2_rn((f1.x - mean) * rstd * wv.z + bv.z,
                                               (f1.y - mean) * rstd * wv.w + bv.w);
}

// ---------------------------------------------------------------------------
// Attention: q len 1 over 2x2 key patch. fp16 in/out, fp32 math.
// ---------------------------------------------------------------------------
__global__ void attn_kernel(const __half* __restrict__ qh, const __half* __restrict__ kh,
                            const __half* __restrict__ vh, __half* __restrict__ o)
{
    const int r  = blockIdx.x;
    const int n  = r / NQ_TOK;
    const int qi = r - n * NQ_TOK;
    const int ar = qi / 12;
    const int ac = qi - ar * 12;
    const int head = threadIdx.x >> 5, lane = threadIdx.x & 31;
    const size_t qoff = (size_t)r * E_DIM + head * 128 + lane * 4;
    const __half2* qp = (const __half2*)(qh + qoff);
    const float2 q0 = __half22float2(qp[0]), q1 = __half22float2(qp[1]);

    int trow[4];
    #pragma unroll
    for (int j = 0; j < 4; j++)
        trow[j] = n * TN_TOK + (2 * ar + (j >> 1)) * 24 + (2 * ac + (j & 1));

    float s[4];
    #pragma unroll
    for (int j = 0; j < 4; j++) {
        const __half2* kp = (const __half2*)(kh + (size_t)trow[j] * E_DIM + head * 128 + lane * 4);
        const float2 k0 = __half22float2(kp[0]), k1 = __half22float2(kp[1]);
        float d = q0.x * k0.x + q0.y * k0.y + q1.x * k1.x + q1.y * k1.y;
        #pragma unroll
        for (int off = 16; off; off >>= 1) d += __shfl_xor_sync(0xffffffffu, d, off);
        s[j] = d * 0.08838834764831843f;
    }
    const float m = fmaxf(fmaxf(s[0], s[1]), fmaxf(s[2], s[3]));
    float e[4], tot = 0.0f;
    #pragma unroll
    for (int j = 0; j < 4; j++) { e[j] = expf(s[j] - m); tot += e[j]; }
    const float inv = 1.0f / tot;

    float a0 = 0.f, a1 = 0.f, a2 = 0.f, a3 = 0.f;
    #pragma unroll
    for (int j = 0; j < 4; j++) {
        const float pj = e[j] * inv;
        const __half2* vp = (const __half2*)(vh + (size_t)trow[j] * E_DIM + head * 128 + lane * 4);
        const float2 v0 = __half22float2(vp[0]), v1 = __half22float2(vp[1]);
        a0 += pj * v0.x; a1 += pj * v0.y; a2 += pj * v1.x; a3 += pj * v1.y;
    }
    __half2* op = (__half2*)(o + qoff);
    op[0] = __floats2half2_rn(a0, a1);
    op[1] = __floats2half2_rn(a2, a3);
}

// ---------------------------------------------------------------------------
extern "C" void kernel_launch(void* const* d_in, const int* in_sizes, int n_in,
                              void* d_out, int out_size)
{
    const float* x      = (const float*)d_in[0];
    const float* x_feat = (const float*)d_in[1];
    const float* w_q    = (const float*)d_in[2];
    const float* w_k1   = (const float*)d_in[3];
    const float* b_k1   = (const float*)d_in[4];
    const float* w_k2   = (const float*)d_in[5];
    const float* b_k2   = (const float*)d_in[6];
    const float* w_v1   = (const float*)d_in[7];
    const float* b_v1   = (const float*)d_in[8];
    const float* w_v2   = (const float*)d_in[9];
    const float* b_v2   = (const float*)d_in[10];
    const float* ln_q_w = (const float*)d_in[11];
    const float* ln_q_b = (const float*)d_in[12];
    const float* ln_k_w = (const float*)d_in[13];
    const float* ln_k_b = (const float*)d_in[14];
    const float* ln_v_w = (const float*)d_in[15];
    const float* ln_v_b = (const float*)d_in[16];
    const float* in_w   = (const float*)d_in[17];
    const float* in_b   = (const float*)d_in[18];
    const float* out_w  = (const float*)d_in[19];
    const float* out_b  = (const float*)d_in[20];

    __half *h2, *key, *val, *kh, *vh, *qb, *qh, *o, *xr, *xfr, *wt;
    float* bcat;
    cudaGetSymbolAddress((void**)&h2,  g_h2);
    cudaGetSymbolAddress((void**)&key, g_key);
    cudaGetSymbolAddress((void**)&val, g_val);
    cudaGetSymbolAddress((void**)&kh,  g_kh);
    cudaGetSymbolAddress((void**)&vh,  g_vh);
    cudaGetSymbolAddress((void**)&qb,  g_q);
    cudaGetSymbolAddress((void**)&qh,  g_qh);
    cudaGetSymbolAddress((void**)&o,   g_o);
    cudaGetSymbolAddress((void**)&xr,  g_xr);
    cudaGetSymbolAddress((void**)&xfr, g_xfr);
    cudaGetSymbolAddress((void**)&wt,  g_wt);
    cudaGetSymbolAddress((void**)&bcat, g_bcat);

    const size_t MW = 1024ull * 1024ull;
    __half* wt_kv1 = wt;                 // [w_k1 ; w_v1]
    __half* wt_k2  = wt + 2 * MW;
    __half* wt_v2  = wt + 3 * MW;
    __half* wt_q   = wt + 4 * MW;
    __half* wt_in  = wt + 5 * MW;        // 3 MW
    __half* wt_out = wt + 8 * MW;

    const int smem_bytes = STAGES * STAGE_B;  // 81920
    cudaFuncSetAttribute(gemm_f16<0, 0>, cudaFuncAttributeMaxDynamicSharedMemorySize, smem_bytes);
    cudaFuncSetAttribute(gemm_f16<1, 0>, cudaFuncAttributeMaxDynamicSharedMemorySize, smem_bytes);
    cudaFuncSetAttribute(gemm_f16<0, 1>, cudaFuncAttributeMaxDynamicSharedMemorySize, smem_bytes);

    // launch 1: merged conversion prepass
    {
        ConvJobs jobs;
        jobs.j[0] = { (const float4*)x,      (__half2*)xr,      M_SMALL * E_DIM / 4 };
        jobs.j[1] = { (const float4*)x_feat, (__half2*)xfr,     M_BIG   * E_DIM / 4 };
        jobs.j[2] = { (const float4*)w_k1,   (__half2*)wt_kv1,  (int)(MW / 4) };
        jobs.j[3] = { (const float4*)w_v1,   (__half2*)(wt_kv1 + MW), (int)(MW / 4) };
        jobs.j[4] = { (const float4*)w_k2,   (__half2*)wt_k2,   (int)(MW / 4) };
        jobs.j[5] = { (const float4*)w_v2,   (__half2*)wt_v2,   (int)(MW / 4) };
        jobs.j[6] = { (const float4*)w_q,    (__half2*)wt_q,    (int)(MW / 4) };
        jobs.j[7] = { (const float4*)in_w,   (__half2*)wt_in,   (int)(3 * MW / 4) };
        jobs.j[8] = { (const float4*)out_w,  (__half2*)wt_out,  (int)(MW / 4) };
        conv_all_kernel<<<dim3(1024, 9), 256>>>(jobs);
    }
    // launch 2: bias concat
    bias_concat_kernel<<<8, 256>>>(b_k1, b_v1, bcat);

    const dim3 blk(256);
    const dim3 gKV(16, M_BIG / BM);
    const dim3 gBig(8, M_BIG / BM);
    const dim3 gSm(8, M_SMALL / BM);

    // launch 3: merged K1+V1 (gelu) -> h2 [M_BIG x 2048]
    gemm_f16<1, 0><<<gKV, blk, smem_bytes>>>(xfr, E_DIM, wt_kv1, bcat, h2, 2048);
    // launch 4 (ncu capture slot): K2
    gemm_f16<0, 0><<<gBig, blk, smem_bytes>>>(h2, 2048, wt_k2, b_k2, key, E_DIM);
    // launch 5: V2
    gemm_f16<0, 0><<<gBig, blk, smem_bytes>>>(h2 + 1024, 2048, wt_v2, b_v2, val, E_DIM);
    // LNs
    ln_kernel<<<M_BIG, 256>>>(key, ln_k_w, ln_k_b);
    ln_kernel<<<M_BIG, 256>>>(val, ln_v_w, ln_v_b);
    // Q path
    gemm_f16<0, 0><<<gSm, blk, smem_bytes>>>(xr, E_DIM, wt_q, nullptr, qb, E_DIM);
    ln_kernel<<<M_SMALL, 256>>>(qb, ln_q_w, ln_q_b);
    // in_proj
    gemm_f16<0, 0><<<gSm,  blk, smem_bytes>>>(qb,  E_DIM, wt_in,          in_b,        qh, E_DIM);
    gemm_f16<0, 0><<<gBig, blk, smem_bytes>>>(key, E_DIM, wt_in + MW,     in_b + 1024, kh, E_DIM);
    gemm_f16<0, 0><<<gBig, blk, smem_bytes>>>(val, E_DIM, wt_in + 2 * MW, in_b + 2048, vh, E_DIM);
    // attention
    attn_kernel<<<M_SMALL, 256>>>(qh, kh, vh, o);
    // out_proj -> d_out (float)
    gemm_f16<0, 1><<<gSm, blk, smem_bytes>>>(o, E_DIM, wt_out, out_b, d_out, E_DIM);
}